// round 11
// baseline (speedup 1.0000x reference)
#include <cuda_runtime.h>
#include <cstdint>

// ---------------------------------------------------------------------------
// LGNN GINE layer, algebraically collapsed + linearity-split tf32 MMA MLP.
//   lgX  = 0.5*(x[col0]+x[col1])                          (stored tf32-rounded)
//   2x:  S[v]  = sum_{i: col1[i]==v, col0[i]!=col1[i]} relu(lgX[i]+x[v])
//        SW1   = tf32(S) @ W1                             (warp-indep GEMM)
//        lgX   = relu(lgX@W1 + SW1[col0] + b1) @ W2 + b2
//   out  = x + relu( segment_mean(lgX, col1) )
// k_mlp v5: persistent, 12 independent warps (384 thr), weights as packed
// B-fragments in L1-resident GLOBAL memory (1 coalesced LDG.64 per mma),
// smem only for per-warp A tiles + biases. __syncwarp-only main loop.
// ---------------------------------------------------------------------------

#define DD   128
#define DV   32
#define MAXE 200000
#define MAXN 50000
#define TILE 16

__device__ float  g_S0[(size_t)MAXN * DD];
__device__ float  g_S1[(size_t)MAXN * DD];
__device__ float  g_Sf[(size_t)MAXN * DD];
__device__ float  g_SW1[(size_t)MAXN * DD];
__device__ float  g_lgX[(size_t)MAXE * DD];
__device__ float  g_cnt[MAXN];
__device__ float  g_Wr1[DD * DD];     // W1 tf32-rounded, [k][n] (for k_sw1)
__device__ float2 g_Wp[2 * 8192];     // packed B-fragments: [w][kk][n][lane]

// ----------------------------- helpers --------------------------------------
__device__ __forceinline__ uint32_t smem_u32(const void* p) {
    uint32_t a;
    asm("{ .reg .u64 t; cvta.to.shared.u64 t, %1; cvt.u32.u64 %0, t; }"
        : "=r"(a) : "l"(p));
    return a;
}
__device__ __forceinline__ float tf32r(float f) {
    uint32_t u;
    asm("cvt.rna.tf32.f32 %0, %1;" : "=r"(u) : "f"(f));
    return __uint_as_float(u);
}
__device__ __forceinline__ void red_add_v4(float* p, float4 v) {
    asm volatile("red.global.add.v4.f32 [%0], {%1,%2,%3,%4};"
                 :: "l"(p), "f"(v.x), "f"(v.y), "f"(v.z), "f"(v.w) : "memory");
}
__device__ __forceinline__ void mma_tf32(float* d, uint32_t a0, uint32_t a1,
                                         uint32_t a2, uint32_t a3,
                                         uint32_t b0, uint32_t b1) {
    asm volatile(
        "mma.sync.aligned.m16n8k8.row.col.f32.tf32.tf32.f32 "
        "{%0,%1,%2,%3}, {%4,%5,%6,%7}, {%8,%9}, {%0,%1,%2,%3};"
        : "+f"(d[0]), "+f"(d[1]), "+f"(d[2]), "+f"(d[3])
        : "r"(a0), "r"(a1), "r"(a2), "r"(a3), "r"(b0), "r"(b1));
}
__device__ __forceinline__ void cp_async16(uint32_t dst, const void* src) {
    asm volatile("cp.async.cg.shared.global [%0], [%1], 16;"
                 :: "r"(dst), "l"(src) : "memory");
}
#define CP_COMMIT() asm volatile("cp.async.commit_group;" ::: "memory")
#define CP_WAIT0()  asm volatile("cp.async.wait_group 0;"  ::: "memory")

#define LDW 136
// float4-granular XOR swizzle for A: row r, float4-col c4 (0..31), word ofs o
#define SWA(r, c4, o) (((r) << 7) + (((((c4) ^ ((r) & 7))) << 2) | (o)))

// warp GEMM, weights from L1-resident packed global (WP = g_Wp+wsel*8192+lane)
#define WARP_GEMM_G(WP, UA)                                                    \
    _Pragma("unroll 4")                                                        \
    for (int kk = 0; kk < 16; kk++) {                                          \
        uint32_t a0 = (UA)[SWA(ty,     kk * 2,     tx4)];                      \
        uint32_t a1 = (UA)[SWA(ty + 8, kk * 2,     tx4)];                      \
        uint32_t a2 = (UA)[SWA(ty,     kk * 2 + 1, tx4)];                      \
        uint32_t a3 = (UA)[SWA(ty + 8, kk * 2 + 1, tx4)];                      \
        _Pragma("unroll")                                                      \
        for (int n = 0; n < 16; n++) {                                         \
            float2 w = (WP)[(kk * 16 + n) * 32];                               \
            mma_tf32(acc[n], a0, a1, a2, a3,                                   \
                     __float_as_uint(w.x), __float_as_uint(w.y));              \
        }                                                                      \
    }

// smem-weight warp GEMM (k_sw1 only)
#define WARP_GEMM_S(UW, UA)                                                    \
    _Pragma("unroll 4")                                                        \
    for (int kk = 0; kk < 16; kk++) {                                          \
        uint32_t a0 = (UA)[SWA(ty,     kk * 2,     tx4)];                      \
        uint32_t a1 = (UA)[SWA(ty + 8, kk * 2,     tx4)];                      \
        uint32_t a2 = (UA)[SWA(ty,     kk * 2 + 1, tx4)];                      \
        uint32_t a3 = (UA)[SWA(ty + 8, kk * 2 + 1, tx4)];                      \
        _Pragma("unroll")                                                      \
        for (int n = 0; n < 16; n++) {                                         \
            uint32_t b0 = (UW)[(kk * 8 + tx4)     * LDW + 8 * n + ty];         \
            uint32_t b1r = (UW)[(kk * 8 + tx4 + 4) * LDW + 8 * n + ty];        \
            mma_tf32(acc[n], a0, a1, a2, a3, b0, b1r);                         \
        }                                                                      \
    }

// ------- prep: zero scratch/cnt, round W for k_sw1, build packed Wp ---------
__global__ void k_prep(const float* __restrict__ W1, const float* __restrict__ W2,
                       float4* s0, float4* s1, float4* sf, float* cnt,
                       int n4, int n)
{
    int i = blockIdx.x * blockDim.x + threadIdx.x;
    float4 z = make_float4(0.f, 0.f, 0.f, 0.f);
    if (i < n4) { s0[i] = z; s1[i] = z; sf[i] = z; }
    if (i < n)  cnt[i] = 0.f;
    if (i < DD * DD) g_Wr1[i] = tf32r(W1[i]);
    if (i < 2 * 8192) {
        int wsel = i >> 13, r = i & 8191;
        int kk = r >> 9, nn = (r >> 5) & 15, lane = r & 31;
        int tx4 = lane & 3, ty = lane >> 2;
        const float* Ws = wsel ? W2 : W1;
        int k0 = kk * 8 + tx4, col = 8 * nn + ty;
        g_Wp[i] = make_float2(tf32r(Ws[k0 * DD + col]),
                              tf32r(Ws[(k0 + 4) * DD + col]));
    }
}

// ---- init: lgX = tf32r(0.5*(x[c0]+x[c1])); scatter relu -> S0; cnt ---------
__global__ void k_init(const float* __restrict__ x,
                       const int* __restrict__ col0,
                       const int* __restrict__ col1, int E)
{
    int idx = blockIdx.x * blockDim.x + threadIdx.x;
    int e = idx >> 5, q = idx & 31;
    if (e >= E) return;
    int c0 = col0[e], c1 = col1[e];
    const float4* x4 = (const float4*)x;
    float4 a = x4[(size_t)c0 * DV + q];
    float4 b = x4[(size_t)c1 * DV + q];
    float4 r;
    r.x = 0.5f * (a.x + b.x);
    r.y = 0.5f * (a.y + b.y);
    r.z = 0.5f * (a.z + b.z);
    r.w = 0.5f * (a.w + b.w);
    if (c0 != c1) {
        float4 v;
        v.x = fmaxf(r.x + b.x, 0.f);
        v.y = fmaxf(r.y + b.y, 0.f);
        v.z = fmaxf(r.z + b.z, 0.f);
        v.w = fmaxf(r.w + b.w, 0.f);
        red_add_v4(&g_S0[(size_t)c1 * DD + 4 * q], v);
    }
    float4 rr;
    rr.x = tf32r(r.x); rr.y = tf32r(r.y); rr.z = tf32r(r.z); rr.w = tf32r(r.w);
    ((float4*)g_lgX)[(size_t)e * DV + q] = rr;
    if (q == 0) atomicAdd(&g_cnt[c1], 1.0f);
}

// ------------- k_sw1: SW1 = tf32(S) @ W1, warp-independent ------------------
#define SW_WORDS (128 * LDW)
#define SA_WORDS (TILE * 128)
#define SW1_SMEM ((SW_WORDS + 8 * SA_WORDS) * 4)
__global__ void __launch_bounds__(256, 1)
k_sw1(const float* __restrict__ Sin, int nwt, int N)
{
    extern __shared__ float sm[];
    float* sW  = sm;
    float* sAb = sm + SW_WORDS;

    const int tid  = threadIdx.x;
    const int wid  = tid >> 5, lane = tid & 31;
    const int ty   = lane >> 2, tx4 = lane & 3;
    const int srow = lane >> 1, hb = lane & 1;

    float* sA = sAb + wid * SA_WORDS;
    const uint32_t* uA = (const uint32_t*)sA;
    const uint32_t* uW = (const uint32_t*)sW;

    #pragma unroll
    for (int i = tid; i < 4096; i += 256) {
        int k = i >> 5, n4 = i & 31;
        *(float4*)&sW[k * LDW + 4 * n4] = ((const float4*)g_Wr1)[i];
    }
    __syncthreads();

    int wt = blockIdx.x * 8 + wid;
    if (wt >= nwt) return;
    const int row0 = wt * TILE;

    {
        int gr = row0 + srow;
        if (gr >= N) gr = N - 1;
        const float4* src = (const float4*)&Sin[(size_t)gr * DD + hb * 64];
        #pragma unroll
        for (int u = 0; u < 16; u++) {
            float4 s = src[u];
            float4 v;
            v.x = tf32r(s.x); v.y = tf32r(s.y);
            v.z = tf32r(s.z); v.w = tf32r(s.w);
            *(float4*)&sA[SWA(srow, hb * 16 + u, 0)] = v;
        }
    }
    __syncwarp();

    float acc[16][4];
    #pragma unroll
    for (int n = 0; n < 16; n++)
        #pragma unroll
        for (int j = 0; j < 4; j++) acc[n][j] = 0.f;

    WARP_GEMM_S(uW, uA);
    __syncwarp();

    #pragma unroll
    for (int n = 0; n < 16; n++) {
        int c4 = 2 * n + (tx4 >> 1), o = (2 * tx4) & 3;
        *(float2*)&sA[SWA(ty, c4, o)]     = make_float2(acc[n][0], acc[n][1]);
        *(float2*)&sA[SWA(ty + 8, c4, o)] = make_float2(acc[n][2], acc[n][3]);
    }
    __syncwarp();

    {
        int gr = row0 + srow;
        if (gr < N) {
            #pragma unroll
            for (int j = 0; j < 16; j++) {
                float4 o = *(float4*)&sA[SWA(srow, hb * 16 + j, 0)];
                *(float4*)&g_SW1[(size_t)gr * DD + hb * 64 + 4 * j] = o;
            }
        }
    }
}

// ----------- persistent fused MLP: 12 warps, L1-resident weights ------------
#define MLPW 12
#define MLP_THREADS (MLPW * 32)
#define MLP_SMEM ((256 + MLPW * SA_WORDS) * 4)   // biases + A buffers ~99.3KB

__global__ void __launch_bounds__(MLP_THREADS, 1)
k_mlp(const int* __restrict__ col0, const int* __restrict__ col1,
      const float* __restrict__ x,
      const float* __restrict__ b1, const float* __restrict__ b2,
      float* __restrict__ Sout,
      int E, int final_mode, int ntiles, int tstride)
{
    extern __shared__ float sm[];
    float* sB1 = sm;                 // [128]
    float* sB2 = sm + 128;           // [128]
    float* sAb = sm + 256;

    const int tid  = threadIdx.x;
    const int wid  = tid >> 5, lane = tid & 31;
    const int ty   = lane >> 2, tx4 = lane & 3;   // fragment coords
    const int srow = lane >> 1;                   // row-phase row (0..15)
    const int hb   = lane & 1;                    // row-phase half (64 words)

    float* sA = sAb + wid * SA_WORDS;
    const uint32_t* uA = (const uint32_t*)sA;
    const uint32_t sAu = smem_u32(sA);
    const float2* Wp1 = g_Wp + lane;          // W1 fragments, this lane
    const float2* Wp2 = g_Wp + 8192 + lane;   // W2 fragments

    if (tid < 128) { sB1[tid] = b1[tid]; sB2[tid] = b2[tid]; }
    __syncthreads();

    int tile = blockIdx.x * MLPW + wid;

    // prologue: stage first tile (cp.async, swizzled dst)
    if (tile < ntiles) {
        int gr = tile * TILE + srow;
        if (gr >= E) gr = E - 1;
        const float* src = &g_lgX[(size_t)gr * DD + hb * 64];
        #pragma unroll
        for (int u = 0; u < 16; u++)
            cp_async16(sAu + 4 * SWA(srow, hb * 16 + u, 0), src + 4 * u);
        CP_COMMIT();
    }

    for (; tile < ntiles; tile += tstride) {
        const int row0 = tile * TILE;
        int ra = row0 + ty, rbq = row0 + ty + 8;
        int c0a = col0[ra < E ? ra : E - 1];
        int c0b = col0[rbq < E ? rbq : E - 1];
        int grr = row0 + srow;
        int myc0 = col0[grr < E ? grr : E - 1];
        int myc1 = col1[grr < E ? grr : E - 1];

        CP_WAIT0();
        __syncwarp();

        float acc[16][4];
        #pragma unroll
        for (int n = 0; n < 16; n++)
            #pragma unroll
            for (int j = 0; j < 4; j++) acc[n][j] = 0.f;

        // ---------------- GEMM 1: O1 = lgX @ W1 ----------------
        WARP_GEMM_G(Wp1, uA);
        __syncwarp();

        // epilogue 1: T = tf32r(relu(O1 + SW1[col0] + b1)) -> sA
        {
            const float* swa = &g_SW1[(size_t)c0a * DD];
            const float* swb = &g_SW1[(size_t)c0b * DD];
            #pragma unroll
            for (int n = 0; n < 16; n++) {
                int cc = 8 * n + 2 * tx4;
                float2 bb = *(const float2*)&sB1[cc];
                float2 s0 = *(const float2*)&swa[cc];
                float2 s1 = *(const float2*)&swb[cc];
                float2 t0, t1;
                t0.x = tf32r(fmaxf(acc[n][0] + s0.x + bb.x, 0.f));
                t0.y = tf32r(fmaxf(acc[n][1] + s0.y + bb.y, 0.f));
                t1.x = tf32r(fmaxf(acc[n][2] + s1.x + bb.x, 0.f));
                t1.y = tf32r(fmaxf(acc[n][3] + s1.y + bb.y, 0.f));
                int c4 = 2 * n + (tx4 >> 1), o = (2 * tx4) & 3;
                *(float2*)&sA[SWA(ty,     c4, o)] = t0;
                *(float2*)&sA[SWA(ty + 8, c4, o)] = t1;
                acc[n][0] = 0.f; acc[n][1] = 0.f;
                acc[n][2] = 0.f; acc[n][3] = 0.f;
            }
        }
        __syncwarp();

        // ---------------- GEMM 2: O2 = T @ W2 ----------------
        WARP_GEMM_G(Wp2, uA);
        __syncwarp();

        // O2 + b2 -> sA (row-major, unrounded)
        #pragma unroll
        for (int n = 0; n < 16; n++) {
            int cc = 8 * n + 2 * tx4;
            float2 bb = *(const float2*)&sB2[cc];
            int c4 = 2 * n + (tx4 >> 1), o = (2 * tx4) & 3;
            *(float2*)&sA[SWA(ty, c4, o)] =
                make_float2(acc[n][0] + bb.x, acc[n][1] + bb.y);
            *(float2*)&sA[SWA(ty + 8, c4, o)] =
                make_float2(acc[n][2] + bb.x, acc[n][3] + bb.y);
        }
        __syncwarp();

        // pull own row-half into registers
        float4 o[16];
        #pragma unroll
        for (int j = 0; j < 16; j++)
            o[j] = *(float4*)&sA[SWA(srow, hb * 16 + j, 0)];
        __syncwarp();

        // stage next tile (overlaps global epilogue)
        {
            int nt = tile + tstride;
            if (nt < ntiles) {
                int g2 = nt * TILE + srow;
                if (g2 >= E) g2 = E - 1;
                const float* src = &g_lgX[(size_t)g2 * DD + hb * 64];
                #pragma unroll
                for (int u = 0; u < 16; u++)
                    cp_async16(sAu + 4 * SWA(srow, hb * 16 + u, 0), src + 4 * u);
                CP_COMMIT();
            }
        }

        // global epilogue: write lgX tf32 (unless final); fused scatter
        if (grr < E) {
            bool emit = final_mode ? true : (myc0 != myc1);
            const float* xp  = &x[(size_t)myc1 * DD + hb * 64];
            float* sop = &Sout[(size_t)myc1 * DD + hb * 64];
            float* lxp = &g_lgX[(size_t)grr * DD + hb * 64];
            #pragma unroll
            for (int j = 0; j < 16; j++) {
                float4 ov = o[j];
                if (!final_mode) {
                    float4 rr;
                    rr.x = tf32r(ov.x); rr.y = tf32r(ov.y);
                    rr.z = tf32r(ov.z); rr.w = tf32r(ov.w);
                    *(float4*)&lxp[4 * j] = rr;
                    if (emit) {
                        float4 xs = *(const float4*)&xp[4 * j];
                        float4 v;
                        v.x = fmaxf(ov.x + xs.x, 0.f);
                        v.y = fmaxf(ov.y + xs.y, 0.f);
                        v.z = fmaxf(ov.z + xs.z, 0.f);
                        v.w = fmaxf(ov.w + xs.w, 0.f);
                        red_add_v4(&sop[4 * j], v);
                    }
                } else {
                    red_add_v4(&sop[4 * j], ov);
                }
            }
        }
    }
}

// ----------------------- out = x + relu(Sf/cnt or 0) ------------------------
__global__ void k_fout(const float* __restrict__ x, float* __restrict__ out, int N)
{
    int idx = blockIdx.x * blockDim.x + threadIdx.x;
    int v = idx >> 5, q = idx & 31;
    if (v >= N) return;
    float c   = g_cnt[v];
    float inv = (c > 0.f) ? (1.f / c) : 0.f;
    float4 s  = ((const float4*)g_Sf)[(size_t)v * DV + q];
    float4 xv = ((const float4*)x)[(size_t)v * DV + q];
    float4 o;
    o.x = xv.x + fmaxf(s.x * inv, 0.f);
    o.y = xv.y + fmaxf(s.y * inv, 0.f);
    o.z = xv.z + fmaxf(s.z * inv, 0.f);
    o.w = xv.w + fmaxf(s.w * inv, 0.f);
    ((float4*)out)[(size_t)v * DV + q] = o;
}

// ---------------------------------------------------------------------------
extern "C" void kernel_launch(void* const* d_in, const int* in_sizes, int n_in,
                              void* d_out, int out_size)
{
    const float* x    = (const float*)d_in[0];
    const float* W1   = (const float*)d_in[1];
    const float* b1   = (const float*)d_in[2];
    const float* W2   = (const float*)d_in[3];
    const float* b2   = (const float*)d_in[4];
    const int*   col0 = (const int*)d_in[5];
    const int*   col1 = (const int*)d_in[6];
    // lg_src / lg_dst / edge_attr_idx are algebraically redundant.

    const int E = in_sizes[5];
    const int N = in_sizes[0] / DD;
    float* out = (float*)d_out;

    void *pS0, *pS1, *pSf, *pC;
    cudaGetSymbolAddress(&pS0, g_S0);
    cudaGetSymbolAddress(&pS1, g_S1);
    cudaGetSymbolAddress(&pSf, g_Sf);
    cudaGetSymbolAddress(&pC,  g_cnt);

    cudaFuncSetAttribute((const void*)k_mlp,
                         cudaFuncAttributeMaxDynamicSharedMemorySize, MLP_SMEM);
    cudaFuncSetAttribute((const void*)k_sw1,
                         cudaFuncAttributeMaxDynamicSharedMemorySize, SW1_SMEM);

    int smcount = 148;
    cudaDeviceGetAttribute(&smcount, cudaDevAttrMultiProcessorCount, 0);

    const int tpb = 256;
    const int nbE = (E * 32 + tpb - 1) / tpb;
    const int nbN = (N * 32 + tpb - 1) / tpb;
    const int ntiles  = (E + TILE - 1) / TILE;
    const int nwt     = (N + TILE - 1) / TILE;
    const int nbS     = (nwt + 7) / 8;
    const int tstride = MLPW * smcount;

    // launch order puts the first k_mlp at kernel-launch slot 4 (ncu capture)
    k_prep<<<(N * 32 + tpb - 1) / tpb, tpb>>>(W1, W2, (float4*)pS0, (float4*)pS1,
                                              (float4*)pSf, (float*)pC,
                                              N * 32, N);
    k_init<<<nbE, tpb>>>(x, col0, col1, E);

    k_sw1<<<nbS, tpb, SW1_SMEM>>>((const float*)pS0, nwt, N);
    k_mlp<<<smcount, MLP_THREADS, MLP_SMEM>>>(col0, col1, x, b1, b2,
                                              (float*)pS1, E, 0, ntiles, tstride);
    k_sw1<<<nbS, tpb, SW1_SMEM>>>((const float*)pS1, nwt, N);
    k_mlp<<<smcount, MLP_THREADS, MLP_SMEM>>>(col0, col1, x, b1, b2,
                                              (float*)pSf, E, 1, ntiles, tstride);
    k_fout<<<nbN, tpb>>>(x, out, N);
}

// round 12
// speedup vs baseline: 1.0268x; 1.0268x over previous
#include <cuda_runtime.h>
#include <cstdint>

// ---------------------------------------------------------------------------
// LGNN GINE layer, algebraically collapsed + linearity-split tf32 MMA MLP.
//   lgX  = 0.5*(x[col0]+x[col1])                          (stored tf32-rounded)
//   2x:  S[v]  = sum_{i: col1[i]==v, col0[i]!=col1[i]} relu(lgX[i]+x[v])
//        SW1   = tf32(S) @ W1                             (warp-indep GEMM)
//        lgX   = relu(lgX@W1 + SW1[col0] + b1) @ W2 + b2
//   out  = x + relu( segment_mean(lgX, col1) )
// k_mlp v6: persistent, 6 independent warps (192 thr), 32-row warp tiles
// (each weight B-fragment feeds 2 mmas -> half the L1 weight traffic),
// packed weights LDG'd from a fully-L1-resident global layout.
// ---------------------------------------------------------------------------

#define DD   128
#define DV   32
#define MAXE 200000
#define MAXN 50000
#define TILE 32

__device__ float  g_S0[(size_t)MAXN * DD];
__device__ float  g_S1[(size_t)MAXN * DD];
__device__ float  g_Sf[(size_t)MAXN * DD];
__device__ float  g_SW1[(size_t)MAXN * DD];
__device__ float  g_lgX[(size_t)MAXE * DD];
__device__ float  g_cnt[MAXN];
__device__ float  g_Wr1[DD * DD];     // W1 tf32-rounded, [k][n] (for k_sw1)
__device__ float2 g_Wp[2 * 8192];     // packed B-fragments: [w][kk][n][lane]

// ----------------------------- helpers --------------------------------------
__device__ __forceinline__ uint32_t smem_u32(const void* p) {
    uint32_t a;
    asm("{ .reg .u64 t; cvta.to.shared.u64 t, %1; cvt.u32.u64 %0, t; }"
        : "=r"(a) : "l"(p));
    return a;
}
__device__ __forceinline__ float tf32r(float f) {
    uint32_t u;
    asm("cvt.rna.tf32.f32 %0, %1;" : "=r"(u) : "f"(f));
    return __uint_as_float(u);
}
__device__ __forceinline__ void red_add_v4(float* p, float4 v) {
    asm volatile("red.global.add.v4.f32 [%0], {%1,%2,%3,%4};"
                 :: "l"(p), "f"(v.x), "f"(v.y), "f"(v.z), "f"(v.w) : "memory");
}
__device__ __forceinline__ void mma_tf32(float* d, uint32_t a0, uint32_t a1,
                                         uint32_t a2, uint32_t a3,
                                         uint32_t b0, uint32_t b1) {
    asm volatile(
        "mma.sync.aligned.m16n8k8.row.col.f32.tf32.tf32.f32 "
        "{%0,%1,%2,%3}, {%4,%5,%6,%7}, {%8,%9}, {%0,%1,%2,%3};"
        : "+f"(d[0]), "+f"(d[1]), "+f"(d[2]), "+f"(d[3])
        : "r"(a0), "r"(a1), "r"(a2), "r"(a3), "r"(b0), "r"(b1));
}
__device__ __forceinline__ void cp_async16(uint32_t dst, const void* src) {
    asm volatile("cp.async.cg.shared.global [%0], [%1], 16;"
                 :: "r"(dst), "l"(src) : "memory");
}
#define CP_COMMIT() asm volatile("cp.async.commit_group;" ::: "memory")
#define CP_WAIT0()  asm volatile("cp.async.wait_group 0;"  ::: "memory")

#define LDW 136
// float4-granular XOR swizzle for A: row r (0..31), float4-col c4, word ofs o
#define SWA(r, c4, o) (((r) << 7) + (((((c4) ^ ((r) & 7))) << 2) | (o)))

// warp GEMM, 32 rows: weights from L1-resident packed global, each B frag
// feeds 2 mmas (m-tiles at rows +0/+8 and +16/+24)
#define WARP_GEMM_G2(WP, UA)                                                   \
    _Pragma("unroll 2")                                                        \
    for (int kk = 0; kk < 16; kk++) {                                          \
        uint32_t a00 = (UA)[SWA(ty,      kk * 2,     tx4)];                    \
        uint32_t a01 = (UA)[SWA(ty + 8,  kk * 2,     tx4)];                    \
        uint32_t a02 = (UA)[SWA(ty,      kk * 2 + 1, tx4)];                    \
        uint32_t a03 = (UA)[SWA(ty + 8,  kk * 2 + 1, tx4)];                    \
        uint32_t a10 = (UA)[SWA(ty + 16, kk * 2,     tx4)];                    \
        uint32_t a11 = (UA)[SWA(ty + 24, kk * 2,     tx4)];                    \
        uint32_t a12 = (UA)[SWA(ty + 16, kk * 2 + 1, tx4)];                    \
        uint32_t a13 = (UA)[SWA(ty + 24, kk * 2 + 1, tx4)];                    \
        _Pragma("unroll")                                                      \
        for (int n = 0; n < 16; n++) {                                         \
            float2 w = (WP)[(kk * 16 + n) * 32];                               \
            uint32_t b0 = __float_as_uint(w.x), b1v = __float_as_uint(w.y);    \
            mma_tf32(acc[0][n], a00, a01, a02, a03, b0, b1v);                  \
            mma_tf32(acc[1][n], a10, a11, a12, a13, b0, b1v);                  \
        }                                                                      \
    }

// smem-weight warp GEMM (k_sw1 only, 16-row tiles)
#define WARP_GEMM_S(UW, UA)                                                    \
    _Pragma("unroll 4")                                                        \
    for (int kk = 0; kk < 16; kk++) {                                          \
        uint32_t a0 = (UA)[SWA(ty,     kk * 2,     tx4)];                      \
        uint32_t a1 = (UA)[SWA(ty + 8, kk * 2,     tx4)];                      \
        uint32_t a2 = (UA)[SWA(ty,     kk * 2 + 1, tx4)];                      \
        uint32_t a3 = (UA)[SWA(ty + 8, kk * 2 + 1, tx4)];                      \
        _Pragma("unroll")                                                      \
        for (int n = 0; n < 16; n++) {                                         \
            uint32_t b0 = (UW)[(kk * 8 + tx4)     * LDW + 8 * n + ty];         \
            uint32_t b1r = (UW)[(kk * 8 + tx4 + 4) * LDW + 8 * n + ty];        \
            mma_tf32(acc[n], a0, a1, a2, a3, b0, b1r);                         \
        }                                                                      \
    }

// ------- prep: zero scratch/cnt, round W for k_sw1, build packed Wp ---------
__global__ void k_prep(const float* __restrict__ W1, const float* __restrict__ W2,
                       float4* s0, float4* s1, float4* sf, float* cnt,
                       int n4, int n)
{
    int i = blockIdx.x * blockDim.x + threadIdx.x;
    float4 z = make_float4(0.f, 0.f, 0.f, 0.f);
    if (i < n4) { s0[i] = z; s1[i] = z; sf[i] = z; }
    if (i < n)  cnt[i] = 0.f;
    if (i < DD * DD) g_Wr1[i] = tf32r(W1[i]);
    if (i < 2 * 8192) {
        int wsel = i >> 13, r = i & 8191;
        int kk = r >> 9, nn = (r >> 5) & 15, lane = r & 31;
        int tx4 = lane & 3, ty = lane >> 2;
        const float* Ws = wsel ? W2 : W1;
        int k0 = kk * 8 + tx4, col = 8 * nn + ty;
        g_Wp[i] = make_float2(tf32r(Ws[k0 * DD + col]),
                              tf32r(Ws[(k0 + 4) * DD + col]));
    }
}

// ---- init: lgX = tf32r(0.5*(x[c0]+x[c1])); scatter relu -> S0; cnt ---------
__global__ void k_init(const float* __restrict__ x,
                       const int* __restrict__ col0,
                       const int* __restrict__ col1, int E)
{
    int idx = blockIdx.x * blockDim.x + threadIdx.x;
    int e = idx >> 5, q = idx & 31;
    if (e >= E) return;
    int c0 = col0[e], c1 = col1[e];
    const float4* x4 = (const float4*)x;
    float4 a = x4[(size_t)c0 * DV + q];
    float4 b = x4[(size_t)c1 * DV + q];
    float4 r;
    r.x = 0.5f * (a.x + b.x);
    r.y = 0.5f * (a.y + b.y);
    r.z = 0.5f * (a.z + b.z);
    r.w = 0.5f * (a.w + b.w);
    if (c0 != c1) {
        float4 v;
        v.x = fmaxf(r.x + b.x, 0.f);
        v.y = fmaxf(r.y + b.y, 0.f);
        v.z = fmaxf(r.z + b.z, 0.f);
        v.w = fmaxf(r.w + b.w, 0.f);
        red_add_v4(&g_S0[(size_t)c1 * DD + 4 * q], v);
    }
    float4 rr;
    rr.x = tf32r(r.x); rr.y = tf32r(r.y); rr.z = tf32r(r.z); rr.w = tf32r(r.w);
    ((float4*)g_lgX)[(size_t)e * DV + q] = rr;
    if (q == 0) atomicAdd(&g_cnt[c1], 1.0f);
}

// ------------- k_sw1: SW1 = tf32(S) @ W1, warp-independent ------------------
#define SW_WORDS (128 * LDW)
#define SA16_WORDS (16 * 128)
#define SW1_SMEM ((SW_WORDS + 8 * SA16_WORDS) * 4)
__global__ void __launch_bounds__(256, 1)
k_sw1(const float* __restrict__ Sin, int nwt, int N)
{
    extern __shared__ float sm[];
    float* sW  = sm;
    float* sAb = sm + SW_WORDS;

    const int tid  = threadIdx.x;
    const int wid  = tid >> 5, lane = tid & 31;
    const int ty   = lane >> 2, tx4 = lane & 3;
    const int srow = lane >> 1, hb = lane & 1;

    float* sA = sAb + wid * SA16_WORDS;
    const uint32_t* uA = (const uint32_t*)sA;
    const uint32_t* uW = (const uint32_t*)sW;

    #pragma unroll
    for (int i = tid; i < 4096; i += 256) {
        int k = i >> 5, n4 = i & 31;
        *(float4*)&sW[k * LDW + 4 * n4] = ((const float4*)g_Wr1)[i];
    }
    __syncthreads();

    int wt = blockIdx.x * 8 + wid;
    if (wt >= nwt) return;
    const int row0 = wt * 16;

    {
        int gr = row0 + srow;
        if (gr >= N) gr = N - 1;
        const float4* src = (const float4*)&Sin[(size_t)gr * DD + hb * 64];
        #pragma unroll
        for (int u = 0; u < 16; u++) {
            float4 s = src[u];
            float4 v;
            v.x = tf32r(s.x); v.y = tf32r(s.y);
            v.z = tf32r(s.z); v.w = tf32r(s.w);
            *(float4*)&sA[SWA(srow, hb * 16 + u, 0)] = v;
        }
    }
    __syncwarp();

    float acc[16][4];
    #pragma unroll
    for (int n = 0; n < 16; n++)
        #pragma unroll
        for (int j = 0; j < 4; j++) acc[n][j] = 0.f;

    WARP_GEMM_S(uW, uA);
    __syncwarp();

    #pragma unroll
    for (int n = 0; n < 16; n++) {
        int c4 = 2 * n + (tx4 >> 1), o = (2 * tx4) & 3;
        *(float2*)&sA[SWA(ty, c4, o)]     = make_float2(acc[n][0], acc[n][1]);
        *(float2*)&sA[SWA(ty + 8, c4, o)] = make_float2(acc[n][2], acc[n][3]);
    }
    __syncwarp();

    {
        int gr = row0 + srow;
        if (gr < N) {
            #pragma unroll
            for (int j = 0; j < 16; j++) {
                float4 o = *(float4*)&sA[SWA(srow, hb * 16 + j, 0)];
                *(float4*)&g_SW1[(size_t)gr * DD + hb * 64 + 4 * j] = o;
            }
        }
    }
}

// ------- persistent fused MLP: 6 warps, 32-row tiles, L1 weights ------------
#define MLPW 6
#define MLP_THREADS (MLPW * 32)
#define SA_WORDS (TILE * 128)                    // 4096 words per warp
#define MLP_SMEM ((256 + MLPW * SA_WORDS) * 4)   // ~99.3 KB

__global__ void __launch_bounds__(MLP_THREADS, 1)
k_mlp(const int* __restrict__ col0, const int* __restrict__ col1,
      const float* __restrict__ x,
      const float* __restrict__ b1, const float* __restrict__ b2,
      float* __restrict__ Sout,
      int E, int final_mode, int ntiles, int tstride)
{
    extern __shared__ float sm[];
    float* sB1 = sm;                 // [128]
    float* sB2 = sm + 128;           // [128]
    float* sAb = sm + 256;

    const int tid  = threadIdx.x;
    const int wid  = tid >> 5, lane = tid & 31;
    const int ty   = lane >> 2, tx4 = lane & 3;   // fragment coords

    float* sA = sAb + wid * SA_WORDS;
    const uint32_t* uA = (const uint32_t*)sA;
    const uint32_t sAu = smem_u32(sA);
    const float2* Wp1 = g_Wp + lane;          // W1 fragments, this lane
    const float2* Wp2 = g_Wp + 8192 + lane;   // W2 fragments

    if (tid < 128) { sB1[tid] = b1[tid]; sB2[tid] = b2[tid]; }
    __syncthreads();

    int tile = blockIdx.x * MLPW + wid;

    // prologue: stage first tile (one full row per lane, swizzled cp.async)
    if (tile < ntiles) {
        int gr = tile * TILE + lane;
        if (gr >= E) gr = E - 1;
        const float* src = &g_lgX[(size_t)gr * DD];
        #pragma unroll
        for (int u = 0; u < 32; u++)
            cp_async16(sAu + 4 * SWA(lane, u, 0), src + 4 * u);
        CP_COMMIT();
    }

    for (; tile < ntiles; tile += tstride) {
        const int row0 = tile * TILE;
        // fragment-row col0 indices (epilogue 1): rows ty, ty+8, ty+16, ty+24
        int r0a = row0 + ty,      r0b = row0 + ty + 8;
        int r1a = row0 + ty + 16, r1b = row0 + ty + 24;
        int c00 = col0[r0a < E ? r0a : E - 1];
        int c01 = col0[r0b < E ? r0b : E - 1];
        int c10 = col0[r1a < E ? r1a : E - 1];
        int c11 = col0[r1b < E ? r1b : E - 1];
        // row-phase indices (epilogue 2): one row per lane
        int grr = row0 + lane;
        int myc0 = col0[grr < E ? grr : E - 1];
        int myc1 = col1[grr < E ? grr : E - 1];

        CP_WAIT0();
        __syncwarp();

        float acc[2][16][4];
        #pragma unroll
        for (int m = 0; m < 2; m++)
            #pragma unroll
            for (int n = 0; n < 16; n++)
                #pragma unroll
                for (int j = 0; j < 4; j++) acc[m][n][j] = 0.f;

        // ---------------- GEMM 1: O1 = lgX @ W1 ----------------
        WARP_GEMM_G2(Wp1, uA);
        __syncwarp();

        // epilogue 1: T = tf32r(relu(O1 + SW1[col0] + b1)) -> sA
        {
            const float* sw00 = &g_SW1[(size_t)c00 * DD];
            const float* sw01 = &g_SW1[(size_t)c01 * DD];
            const float* sw10 = &g_SW1[(size_t)c10 * DD];
            const float* sw11 = &g_SW1[(size_t)c11 * DD];
            #pragma unroll
            for (int n = 0; n < 16; n++) {
                int cc = 8 * n + 2 * tx4;
                float2 bb = *(const float2*)&sB1[cc];
                int c4 = 2 * n + (tx4 >> 1), o = (2 * tx4) & 3;
                {
                    float2 s0 = *(const float2*)&sw00[cc];
                    float2 s1 = *(const float2*)&sw01[cc];
                    float2 t0, t1;
                    t0.x = tf32r(fmaxf(acc[0][n][0] + s0.x + bb.x, 0.f));
                    t0.y = tf32r(fmaxf(acc[0][n][1] + s0.y + bb.y, 0.f));
                    t1.x = tf32r(fmaxf(acc[0][n][2] + s1.x + bb.x, 0.f));
                    t1.y = tf32r(fmaxf(acc[0][n][3] + s1.y + bb.y, 0.f));
                    *(float2*)&sA[SWA(ty,     c4, o)] = t0;
                    *(float2*)&sA[SWA(ty + 8, c4, o)] = t1;
                }
                {
                    float2 s0 = *(const float2*)&sw10[cc];
                    float2 s1 = *(const float2*)&sw11[cc];
                    float2 t0, t1;
                    t0.x = tf32r(fmaxf(acc[1][n][0] + s0.x + bb.x, 0.f));
                    t0.y = tf32r(fmaxf(acc[1][n][1] + s0.y + bb.y, 0.f));
                    t1.x = tf32r(fmaxf(acc[1][n][2] + s1.x + bb.x, 0.f));
                    t1.y = tf32r(fmaxf(acc[1][n][3] + s1.y + bb.y, 0.f));
                    *(float2*)&sA[SWA(ty + 16, c4, o)] = t0;
                    *(float2*)&sA[SWA(ty + 24, c4, o)] = t1;
                }
                #pragma unroll
                for (int m = 0; m < 2; m++)
                    #pragma unroll
                    for (int j = 0; j < 4; j++) acc[m][n][j] = 0.f;
            }
        }
        __syncwarp();

        // ---------------- GEMM 2: O2 = T @ W2 ----------------
        WARP_GEMM_G2(Wp2, uA);
        __syncwarp();

        // O2 + b2 -> sA (row-major, unrounded)
        #pragma unroll
        for (int n = 0; n < 16; n++) {
            int cc = 8 * n + 2 * tx4;
            float2 bb = *(const float2*)&sB2[cc];
            int c4 = 2 * n + (tx4 >> 1), o = (2 * tx4) & 3;
            *(float2*)&sA[SWA(ty, c4, o)] =
                make_float2(acc[0][n][0] + bb.x, acc[0][n][1] + bb.y);
            *(float2*)&sA[SWA(ty + 8, c4, o)] =
                make_float2(acc[0][n][2] + bb.x, acc[0][n][3] + bb.y);
            *(float2*)&sA[SWA(ty + 16, c4, o)] =
                make_float2(acc[1][n][0] + bb.x, acc[1][n][1] + bb.y);
            *(float2*)&sA[SWA(ty + 24, c4, o)] =
                make_float2(acc[1][n][2] + bb.x, acc[1][n][3] + bb.y);
        }
        __syncwarp();

        // global epilogue: one full row per lane, streamed from sA
        if (grr < E) {
            bool emit = final_mode ? true : (myc0 != myc1);
            const float* xp  = &x[(size_t)myc1 * DD];
            float* sop = &Sout[(size_t)myc1 * DD];
            float* lxp = &g_lgX[(size_t)grr * DD];
            #pragma unroll 8
            for (int j = 0; j < 32; j++) {
                float4 ov = *(float4*)&sA[SWA(lane, j, 0)];
                if (!final_mode) {
                    float4 rr;
                    rr.x = tf32r(ov.x); rr.y = tf32r(ov.y);
                    rr.z = tf32r(ov.z); rr.w = tf32r(ov.w);
                    *(float4*)&lxp[4 * j] = rr;
                    if (emit) {
                        float4 xs = *(const float4*)&xp[4 * j];
                        float4 v;
                        v.x = fmaxf(ov.x + xs.x, 0.f);
                        v.y = fmaxf(ov.y + xs.y, 0.f);
                        v.z = fmaxf(ov.z + xs.z, 0.f);
                        v.w = fmaxf(ov.w + xs.w, 0.f);
                        red_add_v4(&sop[4 * j], v);
                    }
                } else {
                    red_add_v4(&sop[4 * j], ov);
                }
            }
        }
        __syncwarp();

        // stage next tile (all sA reads complete)
        {
            int nt = tile + tstride;
            if (nt < ntiles) {
                int g2 = nt * TILE + lane;
                if (g2 >= E) g2 = E - 1;
                const float* src = &g_lgX[(size_t)g2 * DD];
                #pragma unroll
                for (int u = 0; u < 32; u++)
                    cp_async16(sAu + 4 * SWA(lane, u, 0), src + 4 * u);
                CP_COMMIT();
            }
        }
    }
}

// ----------------------- out = x + relu(Sf/cnt or 0) ------------------------
__global__ void k_fout(const float* __restrict__ x, float* __restrict__ out, int N)
{
    int idx = blockIdx.x * blockDim.x + threadIdx.x;
    int v = idx >> 5, q = idx & 31;
    if (v >= N) return;
    float c   = g_cnt[v];
    float inv = (c > 0.f) ? (1.f / c) : 0.f;
    float4 s  = ((const float4*)g_Sf)[(size_t)v * DV + q];
    float4 xv = ((const float4*)x)[(size_t)v * DV + q];
    float4 o;
    o.x = xv.x + fmaxf(s.x * inv, 0.f);
    o.y = xv.y + fmaxf(s.y * inv, 0.f);
    o.z = xv.z + fmaxf(s.z * inv, 0.f);
    o.w = xv.w + fmaxf(s.w * inv, 0.f);
    ((float4*)out)[(size_t)v * DV + q] = o;
}

// ---------------------------------------------------------------------------
extern "C" void kernel_launch(void* const* d_in, const int* in_sizes, int n_in,
                              void* d_out, int out_size)
{
    const float* x    = (const float*)d_in[0];
    const float* W1   = (const float*)d_in[1];
    const float* b1   = (const float*)d_in[2];
    const float* W2   = (const float*)d_in[3];
    const float* b2   = (const float*)d_in[4];
    const int*   col0 = (const int*)d_in[5];
    const int*   col1 = (const int*)d_in[6];
    // lg_src / lg_dst / edge_attr_idx are algebraically redundant.

    const int E = in_sizes[5];
    const int N = in_sizes[0] / DD;
    float* out = (float*)d_out;

    void *pS0, *pS1, *pSf, *pC;
    cudaGetSymbolAddress(&pS0, g_S0);
    cudaGetSymbolAddress(&pS1, g_S1);
    cudaGetSymbolAddress(&pSf, g_Sf);
    cudaGetSymbolAddress(&pC,  g_cnt);

    cudaFuncSetAttribute((const void*)k_mlp,
                         cudaFuncAttributeMaxDynamicSharedMemorySize, MLP_SMEM);
    cudaFuncSetAttribute((const void*)k_sw1,
                         cudaFuncAttributeMaxDynamicSharedMemorySize, SW1_SMEM);

    int smcount = 148;
    cudaDeviceGetAttribute(&smcount, cudaDevAttrMultiProcessorCount, 0);

    const int tpb = 256;
    const int nbE = (E * 32 + tpb - 1) / tpb;
    const int nbN = (N * 32 + tpb - 1) / tpb;
    const int ntiles  = (E + TILE - 1) / TILE;
    const int nwt     = (N + 15) / 16;
    const int nbS     = (nwt + 7) / 8;
    const int tstride = MLPW * smcount;

    // launch order puts the first k_mlp at kernel-launch slot 4 (ncu capture)
    k_prep<<<(N * 32 + tpb - 1) / tpb, tpb>>>(W1, W2, (float4*)pS0, (float4*)pS1,
                                              (float4*)pSf, (float*)pC,
                                              N * 32, N);
    k_init<<<nbE, tpb>>>(x, col0, col1, E);

    k_sw1<<<nbS, tpb, SW1_SMEM>>>((const float*)pS0, nwt, N);
    k_mlp<<<smcount, MLP_THREADS, MLP_SMEM>>>(col0, col1, x, b1, b2,
                                              (float*)pS1, E, 0, ntiles, tstride);
    k_sw1<<<nbS, tpb, SW1_SMEM>>>((const float*)pS1, nwt, N);
    k_mlp<<<smcount, MLP_THREADS, MLP_SMEM>>>(col0, col1, x, b1, b2,
                                              (float*)pSf, E, 1, ntiles, tstride);
    k_fout<<<nbN, tpb>>>(x, out, N);
}

// round 13
// speedup vs baseline: 1.0544x; 1.0269x over previous
#include <cuda_runtime.h>
#include <cstdint>

// ---------------------------------------------------------------------------
// LGNN GINE layer, algebraically collapsed, iteration-1 linearized through x:
//   S0[v]  = sum_{col1[i]==v, c0!=c1} relu(0.5(x[c0]+x[c1]) + x[v]) (k_init)
//   XW1h   = (0.5 x) @ W1 ; SW1_0 = S0 @ W1          (one persistent GEMM)
//   iter1: T = relu(XW1h[c0]+XW1h[c1]+SW1_0[c0]+b1); lgX1 = T@W2+b2
//          scatter S1 += relu(lgX1 + x[c1])           (k_mlp1: ONE gemm)
//   SW1_1  = S1 @ W1
//   iter2: lgX2 = relu(lgX1@W1 + SW1_1[c0] + b1)@W2 + b2 ; Sf += lgX2 (k_mlp2)
//   out    = x + relu(Sf / cnt)
// ---------------------------------------------------------------------------

#define DD   128
#define DV   32
#define MAXE 200000
#define MAXN 50000
#define TILE 16

__device__ float g_S0[(size_t)MAXN * DD];
__device__ float g_S1[(size_t)MAXN * DD];
__device__ float g_Sf[(size_t)MAXN * DD];
__device__ float g_SW1[(size_t)MAXN * DD];
__device__ float g_XW1[(size_t)MAXN * DD];
__device__ float g_lgX[(size_t)MAXE * DD];
__device__ float g_cnt[MAXN];
__device__ float g_Wr1[DD * DD];   // tf32-rounded W1, [k][n]
__device__ float g_Wr2[DD * DD];   // tf32-rounded W2, [k][n]

// ----------------------------- helpers --------------------------------------
__device__ __forceinline__ uint32_t smem_u32(const void* p) {
    uint32_t a;
    asm("{ .reg .u64 t; cvta.to.shared.u64 t, %1; cvt.u32.u64 %0, t; }"
        : "=r"(a) : "l"(p));
    return a;
}
__device__ __forceinline__ float tf32r(float f) {
    uint32_t u;
    asm("cvt.rna.tf32.f32 %0, %1;" : "=r"(u) : "f"(f));
    return __uint_as_float(u);
}
__device__ __forceinline__ void red_add_v4(float* p, float4 v) {
    asm volatile("red.global.add.v4.f32 [%0], {%1,%2,%3,%4};"
                 :: "l"(p), "f"(v.x), "f"(v.y), "f"(v.z), "f"(v.w) : "memory");
}
__device__ __forceinline__ void mma_tf32(float* d, uint32_t a0, uint32_t a1,
                                         uint32_t a2, uint32_t a3,
                                         uint32_t b0, uint32_t b1) {
    asm volatile(
        "mma.sync.aligned.m16n8k8.row.col.f32.tf32.tf32.f32 "
        "{%0,%1,%2,%3}, {%4,%5,%6,%7}, {%8,%9}, {%0,%1,%2,%3};"
        : "+f"(d[0]), "+f"(d[1]), "+f"(d[2]), "+f"(d[3])
        : "r"(a0), "r"(a1), "r"(a2), "r"(a3), "r"(b0), "r"(b1));
}
__device__ __forceinline__ void cp_async16(uint32_t dst, const void* src) {
    asm volatile("cp.async.cg.shared.global [%0], [%1], 16;"
                 :: "r"(dst), "l"(src) : "memory");
}
#define CP_COMMIT() asm volatile("cp.async.commit_group;" ::: "memory")
#define CP_WAIT0()  asm volatile("cp.async.wait_group 0;"  ::: "memory")

#define LDW 136
// float4-granular XOR swizzle for A: row r, float4-col c4 (0..31), word ofs o
#define SWA(r, c4, o) (((r) << 7) + (((((c4) ^ ((r) & 7))) << 2) | (o)))

// warp GEMM: acc[16][4] += Aswz(16x128) @ Wsmem(128x128), frag coords ty/tx4
#define WARP_GEMM_S(UW, UA)                                                    \
    _Pragma("unroll 4")                                                        \
    for (int kk = 0; kk < 16; kk++) {                                          \
        uint32_t a0 = (UA)[SWA(ty,     kk * 2,     tx4)];                      \
        uint32_t a1 = (UA)[SWA(ty + 8, kk * 2,     tx4)];                      \
        uint32_t a2 = (UA)[SWA(ty,     kk * 2 + 1, tx4)];                      \
        uint32_t a3 = (UA)[SWA(ty + 8, kk * 2 + 1, tx4)];                      \
        _Pragma("unroll")                                                      \
        for (int n = 0; n < 16; n++) {                                         \
            uint32_t b0 = (UW)[(kk * 8 + tx4)     * LDW + 8 * n + ty];         \
            uint32_t b1r = (UW)[(kk * 8 + tx4 + 4) * LDW + 8 * n + ty];        \
            mma_tf32(acc[n], a0, a1, a2, a3, b0, b1r);                         \
        }                                                                      \
    }

#define ZERO_ACC16()                                                           \
    _Pragma("unroll")                                                          \
    for (int n = 0; n < 16; n++)                                               \
        _Pragma("unroll")                                                      \
        for (int j = 0; j < 4; j++) acc[n][j] = 0.f;

#define SW_WORDS   (128 * LDW)
#define SA16_WORDS (TILE * 128)

// ------------- prep: zero scratch/cnt + tf32-round weights ------------------
__global__ void k_prep(const float* __restrict__ W1, const float* __restrict__ W2,
                       float4* s0, float4* s1, float4* sf, float* cnt,
                       int n4, int n)
{
    int i = blockIdx.x * blockDim.x + threadIdx.x;
    float4 z = make_float4(0.f, 0.f, 0.f, 0.f);
    if (i < n4) { s0[i] = z; s1[i] = z; sf[i] = z; }
    if (i < n)  cnt[i] = 0.f;
    if (i < DD * DD) {
        g_Wr1[i] = tf32r(W1[i]);
        g_Wr2[i] = tf32r(W2[i]);
    }
}

// ---- init: scatter relu(0.5(x[c0]+x[c1]) + x[c1]) -> S0; cnt (NO lgX) ------
__global__ void k_init(const float* __restrict__ x,
                       const int* __restrict__ col0,
                       const int* __restrict__ col1, int E)
{
    int idx = blockIdx.x * blockDim.x + threadIdx.x;
    int e = idx >> 5, q = idx & 31;
    if (e >= E) return;
    int c0 = col0[e], c1 = col1[e];
    if (q == 0) atomicAdd(&g_cnt[c1], 1.0f);
    if (c0 == c1) return;
    const float4* x4 = (const float4*)x;
    float4 a = x4[(size_t)c0 * DV + q];
    float4 b = x4[(size_t)c1 * DV + q];
    float4 v;
    v.x = fmaxf(0.5f * (a.x + b.x) + b.x, 0.f);
    v.y = fmaxf(0.5f * (a.y + b.y) + b.y, 0.f);
    v.z = fmaxf(0.5f * (a.z + b.z) + b.z, 0.f);
    v.w = fmaxf(0.5f * (a.w + b.w) + b.w, 0.f);
    red_add_v4(&g_S0[(size_t)c1 * DD + 4 * q], v);
}

// ---- k_rw1: persistent row-GEMM vs W1. rows [0,n0): D0 = tf32(c0f*A0)@W1;
//      rows [n0,n0+n1): D1 = tf32(A1)@W1. 8 independent warps per block. -----
#define RW1_SMEM ((SW_WORDS + 8 * SA16_WORDS) * 4)
__global__ void __launch_bounds__(256, 1)
k_rw1(const float* __restrict__ A0, float* __restrict__ D0, int n0,
      const float* __restrict__ A1, float* __restrict__ D1, int n1,
      float c0f)
{
    extern __shared__ float sm[];
    float* sW  = sm;
    float* sAb = sm + SW_WORDS;

    const int tid  = threadIdx.x;
    const int wid  = tid >> 5, lane = tid & 31;
    const int ty   = lane >> 2, tx4 = lane & 3;
    const int srow = lane >> 1, hb = lane & 1;

    float* sA = sAb + wid * SA16_WORDS;
    const uint32_t* uA = (const uint32_t*)sA;
    const uint32_t* uW = (const uint32_t*)sW;

    #pragma unroll
    for (int i = tid; i < 4096; i += 256) {
        int k = i >> 5, n4 = i & 31;
        *(float4*)&sW[k * LDW + 4 * n4] = ((const float4*)g_Wr1)[i];
    }
    __syncthreads();

    const int ntot = n0 + n1;
    const int ntw  = (ntot + TILE - 1) / TILE;
    const int stride = 8 * gridDim.x;

    for (int wt = blockIdx.x * 8 + wid; wt < ntw; wt += stride) {
        const int row0 = wt * TILE;
        const int gr   = row0 + srow;

        // stage (clamped read)
        {
            int R = gr < ntot ? gr : ntot - 1;
            const float* src;
            float cf;
            if (R < n0) { src = &A0[(size_t)R * DD]; cf = c0f; }
            else        { src = &A1[(size_t)(R - n0) * DD]; cf = 1.0f; }
            const float4* s4 = (const float4*)(src + hb * 64);
            #pragma unroll
            for (int u = 0; u < 16; u++) {
                float4 s = s4[u];
                float4 v;
                v.x = tf32r(cf * s.x); v.y = tf32r(cf * s.y);
                v.z = tf32r(cf * s.z); v.w = tf32r(cf * s.w);
                *(float4*)&sA[SWA(srow, hb * 16 + u, 0)] = v;
            }
        }
        __syncwarp();

        float acc[16][4];
        ZERO_ACC16();
        WARP_GEMM_S(uW, uA);
        __syncwarp();

        #pragma unroll
        for (int n = 0; n < 16; n++) {
            int c4 = 2 * n + (tx4 >> 1), o = (2 * tx4) & 3;
            *(float2*)&sA[SWA(ty, c4, o)]     = make_float2(acc[n][0], acc[n][1]);
            *(float2*)&sA[SWA(ty + 8, c4, o)] = make_float2(acc[n][2], acc[n][3]);
        }
        __syncwarp();

        if (gr < ntot) {
            float* dst = (gr < n0) ? &D0[(size_t)gr * DD]
                                   : &D1[(size_t)(gr - n0) * DD];
            dst += hb * 64;
            #pragma unroll
            for (int j = 0; j < 16; j++)
                *(float4*)&dst[4 * j] = *(float4*)&sA[SWA(srow, hb * 16 + j, 0)];
        }
        __syncwarp();
    }
}

// ---- k_mlp1: iteration 1 with GEMM1 replaced by gathers (ONE gemm) ---------
// T = tf32(relu(XW1h[c0]+XW1h[c1]+SW1[c0]+b1)); O2 = T@W2 + b2;
// write lgX = tf32(O2); scatter S1 += relu(O2 + x[c1]) for non-self-loops.
#define MLP1_SMEM ((SW_WORDS + 256 + 8 * SA16_WORDS) * 4)
__global__ void __launch_bounds__(256, 1)
k_mlp1(const int* __restrict__ col0, const int* __restrict__ col1,
       const float* __restrict__ x,
       const float* __restrict__ b1, const float* __restrict__ b2,
       float* __restrict__ Sout,
       int E, int ntiles, int tstride)
{
    extern __shared__ float sm[];
    float* sW2 = sm;
    float* sB1 = sm + SW_WORDS;        // [128]
    float* sB2 = sB1 + 128;            // [128]
    float* sAb = sB2 + 128;

    const int tid  = threadIdx.x;
    const int wid  = tid >> 5, lane = tid & 31;
    const int ty   = lane >> 2, tx4 = lane & 3;
    const int srow = lane >> 1, hb = lane & 1;

    float* sA = sAb + wid * SA16_WORDS;
    const uint32_t* uA = (const uint32_t*)sA;
    const uint32_t* uW = (const uint32_t*)sW2;

    #pragma unroll
    for (int i = tid; i < 4096; i += 256) {
        int k = i >> 5, n4 = i & 31;
        *(float4*)&sW2[k * LDW + 4 * n4] = ((const float4*)g_Wr2)[i];
    }
    if (tid < 128) { sB1[tid] = b1[tid]; sB2[tid] = b2[tid]; }
    __syncthreads();

    for (int tile = blockIdx.x * 8 + wid; tile < ntiles; tile += tstride) {
        const int row0 = tile * TILE;
        const int grr  = row0 + srow;
        const int rcl  = grr < E ? grr : E - 1;
        const int myc0 = col0[rcl];
        const int myc1 = col1[rcl];

        // phase 1: T = tf32(relu(XW1h[c0] + XW1h[c1] + SW1[c0] + b1)) -> sA
        {
            const float4* xw0 = (const float4*)&g_XW1[(size_t)myc0 * DD + hb * 64];
            const float4* xw1 = (const float4*)&g_XW1[(size_t)myc1 * DD + hb * 64];
            const float4* sw  = (const float4*)&g_SW1[(size_t)myc0 * DD + hb * 64];
            const float4* bb4 = (const float4*)&sB1[hb * 64];
            #pragma unroll
            for (int j = 0; j < 16; j++) {
                float4 a = xw0[j], b = xw1[j], s = sw[j], bb = bb4[j];
                float4 t;
                t.x = tf32r(fmaxf(a.x + b.x + s.x + bb.x, 0.f));
                t.y = tf32r(fmaxf(a.y + b.y + s.y + bb.y, 0.f));
                t.z = tf32r(fmaxf(a.z + b.z + s.z + bb.z, 0.f));
                t.w = tf32r(fmaxf(a.w + b.w + s.w + bb.w, 0.f));
                *(float4*)&sA[SWA(srow, hb * 16 + j, 0)] = t;
            }
        }
        __syncwarp();

        float acc[16][4];
        ZERO_ACC16();
        // GEMM: O2 = T @ W2
        WARP_GEMM_S(uW, uA);
        __syncwarp();

        // O2 + b2 -> sA row-major (unrounded)
        #pragma unroll
        for (int n = 0; n < 16; n++) {
            int cc = 8 * n + 2 * tx4;
            float2 bb = *(const float2*)&sB2[cc];
            int c4 = 2 * n + (tx4 >> 1), o = (2 * tx4) & 3;
            *(float2*)&sA[SWA(ty, c4, o)] =
                make_float2(acc[n][0] + bb.x, acc[n][1] + bb.y);
            *(float2*)&sA[SWA(ty + 8, c4, o)] =
                make_float2(acc[n][2] + bb.x, acc[n][3] + bb.y);
        }
        __syncwarp();

        // row epilogue: write lgX tf32; scatter S1 += relu(O2 + x[c1])
        if (grr < E) {
            bool emit = (myc0 != myc1);
            const float* xp  = &x[(size_t)myc1 * DD + hb * 64];
            float* sop = &Sout[(size_t)myc1 * DD + hb * 64];
            float* lxp = &g_lgX[(size_t)grr * DD + hb * 64];
            #pragma unroll
            for (int j = 0; j < 16; j++) {
                float4 ov = *(float4*)&sA[SWA(srow, hb * 16 + j, 0)];
                float4 rr;
                rr.x = tf32r(ov.x); rr.y = tf32r(ov.y);
                rr.z = tf32r(ov.z); rr.w = tf32r(ov.w);
                *(float4*)&lxp[4 * j] = rr;
                if (emit) {
                    float4 xs = *(const float4*)&xp[4 * j];
                    float4 v;
                    v.x = fmaxf(ov.x + xs.x, 0.f);
                    v.y = fmaxf(ov.y + xs.y, 0.f);
                    v.z = fmaxf(ov.z + xs.z, 0.f);
                    v.w = fmaxf(ov.w + xs.w, 0.f);
                    red_add_v4(&sop[4 * j], v);
                }
            }
        }
        __syncwarp();
    }
}

// ---- k_mlp2: iteration 2, full 2-GEMM pipeline (R8 structure, final mode) --
#define MLP2_SMEM ((2 * SW_WORDS + 8 * SA16_WORDS) * 4)   // 204800 B
__global__ void __launch_bounds__(256, 1)
k_mlp2(const int* __restrict__ col0, const int* __restrict__ col1,
       const float* __restrict__ b1, const float* __restrict__ b2,
       float* __restrict__ Sout,
       int E, int ntiles, int tstride)
{
    extern __shared__ float sm[];
    float* sW1 = sm;
    float* sW2 = sm + SW_WORDS;
    float* sAb = sm + 2 * SW_WORDS;

    const int tid  = threadIdx.x;
    const int wid  = tid >> 5, lane = tid & 31;
    const int ty   = lane >> 2, tx4 = lane & 3;
    const int srow = lane >> 1, hb = lane & 1;

    float* sA = sAb + wid * SA16_WORDS;
    const uint32_t* uA  = (const uint32_t*)sA;
    const uint32_t* uW1 = (const uint32_t*)sW1;
    const uint32_t* uW2 = (const uint32_t*)sW2;
    const uint32_t sAu = smem_u32(sA);

    #pragma unroll
    for (int i = tid; i < 4096; i += 256) {
        int k = i >> 5, n4 = i & 31;
        *(float4*)&sW1[k * LDW + 4 * n4] = ((const float4*)g_Wr1)[i];
        *(float4*)&sW2[k * LDW + 4 * n4] = ((const float4*)g_Wr2)[i];
    }
    __syncthreads();

    float2 rb1[16], rb2[16];
    #pragma unroll
    for (int n = 0; n < 16; n++) {
        rb1[n] = *(const float2*)&b1[8 * n + 2 * tx4];
        rb2[n] = *(const float2*)&b2[8 * n + 2 * tx4];
    }

    int tile = blockIdx.x * 8 + wid;

    if (tile < ntiles) {
        int gr = tile * TILE + srow;
        if (gr >= E) gr = E - 1;
        const float* src = &g_lgX[(size_t)gr * DD + hb * 64];
        #pragma unroll
        for (int u = 0; u < 16; u++)
            cp_async16(sAu + 4 * SWA(srow, hb * 16 + u, 0), src + 4 * u);
        CP_COMMIT();
    }

    for (; tile < ntiles; tile += tstride) {
        const int row0 = tile * TILE;
        int ra = row0 + ty, rbq = row0 + ty + 8;
        int c0a = col0[ra < E ? ra : E - 1];
        int c0b = col0[rbq < E ? rbq : E - 1];
        int grr = row0 + srow;
        int myc1 = col1[grr < E ? grr : E - 1];

        CP_WAIT0();
        __syncwarp();

        float acc[16][4];
        ZERO_ACC16();

        // GEMM 1: O1 = lgX @ W1
        WARP_GEMM_S(uW1, uA);
        __syncwarp();

        // epilogue 1: T = tf32r(relu(O1 + SW1[col0] + b1))
        {
            const float* swa = &g_SW1[(size_t)c0a * DD];
            const float* swb = &g_SW1[(size_t)c0b * DD];
            #pragma unroll
            for (int n = 0; n < 16; n++) {
                int cc = 8 * n + 2 * tx4;
                float2 s0 = *(const float2*)&swa[cc];
                float2 s1 = *(const float2*)&swb[cc];
                float2 t0, t1;
                t0.x = tf32r(fmaxf(acc[n][0] + s0.x + rb1[n].x, 0.f));
                t0.y = tf32r(fmaxf(acc[n][1] + s0.y + rb1[n].y, 0.f));
                t1.x = tf32r(fmaxf(acc[n][2] + s1.x + rb1[n].x, 0.f));
                t1.y = tf32r(fmaxf(acc[n][3] + s1.y + rb1[n].y, 0.f));
                int c4 = 2 * n + (tx4 >> 1), o = (2 * tx4) & 3;
                *(float2*)&sA[SWA(ty,     c4, o)] = t0;
                *(float2*)&sA[SWA(ty + 8, c4, o)] = t1;
                acc[n][0] = 0.f; acc[n][1] = 0.f;
                acc[n][2] = 0.f; acc[n][3] = 0.f;
            }
        }
        __syncwarp();

        // GEMM 2: O2 = T @ W2
        WARP_GEMM_S(uW2, uA);
        __syncwarp();

        // O2 + b2 -> sA (row-major)
        #pragma unroll
        for (int n = 0; n < 16; n++) {
            int c4 = 2 * n + (tx4 >> 1), o = (2 * tx4) & 3;
            *(float2*)&sA[SWA(ty, c4, o)] =
                make_float2(acc[n][0] + rb2[n].x, acc[n][1] + rb2[n].y);
            *(float2*)&sA[SWA(ty + 8, c4, o)] =
                make_float2(acc[n][2] + rb2[n].x, acc[n][3] + rb2[n].y);
        }
        __syncwarp();

        float4 o[16];
        #pragma unroll
        for (int j = 0; j < 16; j++)
            o[j] = *(float4*)&sA[SWA(srow, hb * 16 + j, 0)];
        __syncwarp();

        {
            int nt = tile + tstride;
            if (nt < ntiles) {
                int g2 = nt * TILE + srow;
                if (g2 >= E) g2 = E - 1;
                const float* src = &g_lgX[(size_t)g2 * DD + hb * 64];
                #pragma unroll
                for (int u = 0; u < 16; u++)
                    cp_async16(sAu + 4 * SWA(srow, hb * 16 + u, 0), src + 4 * u);
                CP_COMMIT();
            }
        }

        // final scatter: Sf[col1] += O2 (all rows)
        if (grr < E) {
            float* sop = &Sout[(size_t)myc1 * DD + hb * 64];
            #pragma unroll
            for (int j = 0; j < 16; j++)
                red_add_v4(&sop[4 * j], o[j]);
        }
    }
}

// ----------------------- out = x + relu(Sf/cnt or 0) ------------------------
__global__ void k_fout(const float* __restrict__ x, float* __restrict__ out, int N)
{
    int idx = blockIdx.x * blockDim.x + threadIdx.x;
    int v = idx >> 5, q = idx & 31;
    if (v >= N) return;
    float c   = g_cnt[v];
    float inv = (c > 0.f) ? (1.f / c) : 0.f;
    float4 s  = ((const float4*)g_Sf)[(size_t)v * DV + q];
    float4 xv = ((const float4*)x)[(size_t)v * DV + q];
    float4 o;
    o.x = xv.x + fmaxf(s.x * inv, 0.f);
    o.y = xv.y + fmaxf(s.y * inv, 0.f);
    o.z = xv.z + fmaxf(s.z * inv, 0.f);
    o.w = xv.w + fmaxf(s.w * inv, 0.f);
    ((float4*)out)[(size_t)v * DV + q] = o;
}

// ---------------------------------------------------------------------------
extern "C" void kernel_launch(void* const* d_in, const int* in_sizes, int n_in,
                              void* d_out, int out_size)
{
    const float* x    = (const float*)d_in[0];
    const float* W1   = (const float*)d_in[1];
    const float* b1   = (const float*)d_in[2];
    const float* W2   = (const float*)d_in[3];
    const float* b2   = (const float*)d_in[4];
    const int*   col0 = (const int*)d_in[5];
    const int*   col1 = (const int*)d_in[6];
    // lg_src / lg_dst / edge_attr_idx are algebraically redundant.

    const int E = in_sizes[5];
    const int N = in_sizes[0] / DD;
    float* out = (float*)d_out;

    void *pS0, *pS1, *pSf, *pC, *pXW1, *pSW1;
    cudaGetSymbolAddress(&pS0,  g_S0);
    cudaGetSymbolAddress(&pS1,  g_S1);
    cudaGetSymbolAddress(&pSf,  g_Sf);
    cudaGetSymbolAddress(&pC,   g_cnt);
    cudaGetSymbolAddress(&pXW1, g_XW1);
    cudaGetSymbolAddress(&pSW1, g_SW1);

    cudaFuncSetAttribute((const void*)k_rw1,
                         cudaFuncAttributeMaxDynamicSharedMemorySize, RW1_SMEM);
    cudaFuncSetAttribute((const void*)k_mlp1,
                         cudaFuncAttributeMaxDynamicSharedMemorySize, MLP1_SMEM);
    cudaFuncSetAttribute((const void*)k_mlp2,
                         cudaFuncAttributeMaxDynamicSharedMemorySize, MLP2_SMEM);

    int smcount = 148;
    cudaDeviceGetAttribute(&smcount, cudaDevAttrMultiProcessorCount, 0);

    const int tpb = 256;
    const int nbE = (E * 32 + tpb - 1) / tpb;
    const int nbN = (N * 32 + tpb - 1) / tpb;
    const int ntiles  = (E + TILE - 1) / TILE;
    const int tstride = 8 * smcount;

    k_prep<<<(N * 32 + tpb - 1) / tpb, tpb>>>(W1, W2, (float4*)pS0, (float4*)pS1,
                                              (float4*)pSf, (float*)pC,
                                              N * 32, N);
    k_init<<<nbE, tpb>>>(x, col0, col1, E);

    // XW1h = (0.5 x) @ W1 ; SW1_0 = S0 @ W1 (one persistent launch)
    k_rw1<<<smcount, tpb, RW1_SMEM>>>(x, (float*)pXW1, N,
                                      (const float*)pS0, (float*)pSW1, N, 0.5f);
    // iteration 1 (slot 4 for ncu)
    k_mlp1<<<smcount, tpb, MLP1_SMEM>>>(col0, col1, x, b1, b2,
                                        (float*)pS1, E, ntiles, tstride);
    // SW1_1 = S1 @ W1
    k_rw1<<<smcount, tpb, RW1_SMEM>>>((const float*)pS1, (float*)pSW1, N,
                                      (const float*)pS1, (float*)pSW1, 0, 1.0f);
    // iteration 2 (final): Sf += lgX2
    k_mlp2<<<smcount, tpb, MLP2_SMEM>>>(col0, col1, b1, b2,
                                        (float*)pSf, E, ntiles, tstride);
    k_fout<<<nbN, tpb>>>(x, out, N);
}

// round 14
// speedup vs baseline: 1.3131x; 1.2453x over previous
#include <cuda_runtime.h>
#include <cstdint>

// ---------------------------------------------------------------------------
// LGNN GINE layer, algebraically collapsed, iteration-1 linearized through x:
//   S0[v]  = sum_{col1[i]==v, c0!=c1} relu(0.5(x[c0]+x[c1]) + x[v]) (k_init)
//   XW1h   = (0.5 x) @ W1 ; SW1_0 = S0 @ W1          (one persistent GEMM)
//   iter1: T = relu(XW1h[c0]+XW1h[c1]+SW1_0[c0]+b1); lgX1 = T@W2+b2
//          scatter S1 += relu(lgX1 + x[c1])           (k_mlp1: ONE gemm)
//   SW1_1  = S1 @ W1
//   iter2: lgX2 = relu(lgX1@W1 + SW1_1[c0] + b1)@W2 + b2 ; Sf += lgX2 (k_mlp2)
//   out    = x + relu(Sf / cnt)
// v2: ALL random-row gathers/scatters are WARP-COOPERATIVE (one warp-wide
// instruction per 512B row -> 4 L1 lines instead of 16-32). Indices via shfl.
// ---------------------------------------------------------------------------

#define DD   128
#define DV   32
#define MAXE 200000
#define MAXN 50000
#define TILE 16

__device__ float g_S0[(size_t)MAXN * DD];
__device__ float g_S1[(size_t)MAXN * DD];
__device__ float g_Sf[(size_t)MAXN * DD];
__device__ float g_SW1[(size_t)MAXN * DD];
__device__ float g_XW1[(size_t)MAXN * DD];
__device__ float g_lgX[(size_t)MAXE * DD];
__device__ float g_cnt[MAXN];
__device__ float g_Wr1[DD * DD];   // tf32-rounded W1, [k][n]
__device__ float g_Wr2[DD * DD];   // tf32-rounded W2, [k][n]

// ----------------------------- helpers --------------------------------------
__device__ __forceinline__ uint32_t smem_u32(const void* p) {
    uint32_t a;
    asm("{ .reg .u64 t; cvta.to.shared.u64 t, %1; cvt.u32.u64 %0, t; }"
        : "=r"(a) : "l"(p));
    return a;
}
__device__ __forceinline__ float tf32r(float f) {
    uint32_t u;
    asm("cvt.rna.tf32.f32 %0, %1;" : "=r"(u) : "f"(f));
    return __uint_as_float(u);
}
__device__ __forceinline__ void red_add_v4(float* p, float4 v) {
    asm volatile("red.global.add.v4.f32 [%0], {%1,%2,%3,%4};"
                 :: "l"(p), "f"(v.x), "f"(v.y), "f"(v.z), "f"(v.w) : "memory");
}
__device__ __forceinline__ void mma_tf32(float* d, uint32_t a0, uint32_t a1,
                                         uint32_t a2, uint32_t a3,
                                         uint32_t b0, uint32_t b1) {
    asm volatile(
        "mma.sync.aligned.m16n8k8.row.col.f32.tf32.tf32.f32 "
        "{%0,%1,%2,%3}, {%4,%5,%6,%7}, {%8,%9}, {%0,%1,%2,%3};"
        : "+f"(d[0]), "+f"(d[1]), "+f"(d[2]), "+f"(d[3])
        : "r"(a0), "r"(a1), "r"(a2), "r"(a3), "r"(b0), "r"(b1));
}
__device__ __forceinline__ void cp_async16(uint32_t dst, const void* src) {
    asm volatile("cp.async.cg.shared.global [%0], [%1], 16;"
                 :: "r"(dst), "l"(src) : "memory");
}
#define CP_COMMIT() asm volatile("cp.async.commit_group;" ::: "memory")
#define CP_WAIT0()  asm volatile("cp.async.wait_group 0;"  ::: "memory")
#define FULLM 0xffffffffu

#define LDW 136
// float4-granular XOR swizzle for A: row r, float4-col c4 (0..31), word ofs o
#define SWA(r, c4, o) (((r) << 7) + (((((c4) ^ ((r) & 7))) << 2) | (o)))

// warp GEMM: acc[16][4] += Aswz(16x128) @ Wsmem(128x128), frag coords ty/tx4
#define WARP_GEMM_S(UW, UA)                                                    \
    _Pragma("unroll 4")                                                        \
    for (int kk = 0; kk < 16; kk++) {                                          \
        uint32_t a0 = (UA)[SWA(ty,     kk * 2,     tx4)];                      \
        uint32_t a1 = (UA)[SWA(ty + 8, kk * 2,     tx4)];                      \
        uint32_t a2 = (UA)[SWA(ty,     kk * 2 + 1, tx4)];                      \
        uint32_t a3 = (UA)[SWA(ty + 8, kk * 2 + 1, tx4)];                      \
        _Pragma("unroll")                                                      \
        for (int n = 0; n < 16; n++) {                                         \
            uint32_t b0 = (UW)[(kk * 8 + tx4)     * LDW + 8 * n + ty];         \
            uint32_t b1r = (UW)[(kk * 8 + tx4 + 4) * LDW + 8 * n + ty];        \
            mma_tf32(acc[n], a0, a1, a2, a3, b0, b1r);                         \
        }                                                                      \
    }

#define ZERO_ACC16()                                                           \
    _Pragma("unroll")                                                          \
    for (int n = 0; n < 16; n++)                                               \
        _Pragma("unroll")                                                      \
        for (int j = 0; j < 4; j++) acc[n][j] = 0.f;

// fragment accumulators (raw, no bias) -> sA row-major
#define ACC_TO_SA(SA)                                                          \
    _Pragma("unroll")                                                          \
    for (int n = 0; n < 16; n++) {                                             \
        int c4 = 2 * n + (tx4 >> 1), o = (2 * tx4) & 3;                        \
        *(float2*)&(SA)[SWA(ty, c4, o)]     =                                  \
            make_float2(acc[n][0], acc[n][1]);                                 \
        *(float2*)&(SA)[SWA(ty + 8, c4, o)] =                                  \
            make_float2(acc[n][2], acc[n][3]);                                 \
    }

#define SW_WORDS   (128 * LDW)
#define SA16_WORDS (TILE * 128)

// ------------- prep: zero scratch/cnt + tf32-round weights ------------------
__global__ void k_prep(const float* __restrict__ W1, const float* __restrict__ W2,
                       float4* s0, float4* s1, float4* sf, float* cnt,
                       int n4, int n)
{
    int i = blockIdx.x * blockDim.x + threadIdx.x;
    float4 z = make_float4(0.f, 0.f, 0.f, 0.f);
    if (i < n4) { s0[i] = z; s1[i] = z; sf[i] = z; }
    if (i < n)  cnt[i] = 0.f;
    if (i < DD * DD) {
        g_Wr1[i] = tf32r(W1[i]);
        g_Wr2[i] = tf32r(W2[i]);
    }
}

// ---- init: scatter relu(0.5(x[c0]+x[c1]) + x[c1]) -> S0; cnt ---------------
__global__ void k_init(const float* __restrict__ x,
                       const int* __restrict__ col0,
                       const int* __restrict__ col1, int E)
{
    int idx = blockIdx.x * blockDim.x + threadIdx.x;
    int e = idx >> 5, q = idx & 31;
    if (e >= E) return;
    int c0 = col0[e], c1 = col1[e];
    if (q == 0) atomicAdd(&g_cnt[c1], 1.0f);
    if (c0 == c1) return;
    const float4* x4 = (const float4*)x;
    float4 a = x4[(size_t)c0 * DV + q];
    float4 b = x4[(size_t)c1 * DV + q];
    float4 v;
    v.x = fmaxf(0.5f * (a.x + b.x) + b.x, 0.f);
    v.y = fmaxf(0.5f * (a.y + b.y) + b.y, 0.f);
    v.z = fmaxf(0.5f * (a.z + b.z) + b.z, 0.f);
    v.w = fmaxf(0.5f * (a.w + b.w) + b.w, 0.f);
    red_add_v4(&g_S0[(size_t)c1 * DD + 4 * q], v);
}

// ---- k_rw1: persistent row-GEMM vs W1. rows [0,n0): D0 = tf32(c0f*A0)@W1;
//      rows [n0,n0+n1): D1 = tf32(A1)@W1. 8 independent warps per block. -----
#define RW1_SMEM ((SW_WORDS + 8 * SA16_WORDS) * 4)
__global__ void __launch_bounds__(256, 1)
k_rw1(const float* __restrict__ A0, float* __restrict__ D0, int n0,
      const float* __restrict__ A1, float* __restrict__ D1, int n1,
      float c0f)
{
    extern __shared__ float sm[];
    float* sW  = sm;
    float* sAb = sm + SW_WORDS;

    const int tid  = threadIdx.x;
    const int wid  = tid >> 5, lane = tid & 31;
    const int ty   = lane >> 2, tx4 = lane & 3;

    float* sA = sAb + wid * SA16_WORDS;
    const uint32_t* uA = (const uint32_t*)sA;
    const uint32_t* uW = (const uint32_t*)sW;

    #pragma unroll
    for (int i = tid; i < 4096; i += 256) {
        int k = i >> 5, n4 = i & 31;
        *(float4*)&sW[k * LDW + 4 * n4] = ((const float4*)g_Wr1)[i];
    }
    __syncthreads();

    const int ntot = n0 + n1;
    const int ntw  = (ntot + TILE - 1) / TILE;
    const int stride = 8 * gridDim.x;

    for (int wt = blockIdx.x * 8 + wid; wt < ntw; wt += stride) {
        const int row0 = wt * TILE;

        // cooperative stage: warp loads each row contiguously
        #pragma unroll 4
        for (int r = 0; r < 16; r++) {
            int R = row0 + r;
            if (R >= ntot) R = ntot - 1;
            const float* src;
            float cf;
            if (R < n0) { src = &A0[(size_t)R * DD]; cf = c0f; }
            else        { src = &A1[(size_t)(R - n0) * DD]; cf = 1.0f; }
            float4 s = *(const float4*)&src[4 * lane];
            float4 v;
            v.x = tf32r(cf * s.x); v.y = tf32r(cf * s.y);
            v.z = tf32r(cf * s.z); v.w = tf32r(cf * s.w);
            *(float4*)&sA[SWA(r, lane, 0)] = v;
        }
        __syncwarp();

        float acc[16][4];
        ZERO_ACC16();
        WARP_GEMM_S(uW, uA);
        __syncwarp();

        ACC_TO_SA(sA);
        __syncwarp();

        // cooperative store
        #pragma unroll 4
        for (int r = 0; r < 16; r++) {
            int gr = row0 + r;
            if (gr >= ntot) break;
            float* dst = (gr < n0) ? &D0[(size_t)gr * DD]
                                   : &D1[(size_t)(gr - n0) * DD];
            *(float4*)&dst[4 * lane] = *(float4*)&sA[SWA(r, lane, 0)];
        }
        __syncwarp();
    }
}

// ---- k_mlp1: iteration 1, GEMM1 replaced by cooperative row gathers --------
#define MLP1_SMEM ((SW_WORDS + 8 * SA16_WORDS) * 4)
__global__ void __launch_bounds__(256, 1)
k_mlp1(const int* __restrict__ col0, const int* __restrict__ col1,
       const float* __restrict__ x,
       const float* __restrict__ b1, const float* __restrict__ b2,
       float* __restrict__ Sout,
       int E, int ntiles, int tstride)
{
    extern __shared__ float sm[];
    float* sW2 = sm;
    float* sAb = sm + SW_WORDS;

    const int tid  = threadIdx.x;
    const int wid  = tid >> 5, lane = tid & 31;
    const int ty   = lane >> 2, tx4 = lane & 3;

    float* sA = sAb + wid * SA16_WORDS;
    const uint32_t* uA = (const uint32_t*)sA;
    const uint32_t* uW = (const uint32_t*)sW2;

    #pragma unroll
    for (int i = tid; i < 4096; i += 256) {
        int k = i >> 5, n4 = i & 31;
        *(float4*)&sW2[k * LDW + 4 * n4] = ((const float4*)g_Wr2)[i];
    }
    __syncthreads();

    const float4 bb1 = *(const float4*)&b1[4 * lane];
    const float4 bb2 = *(const float4*)&b2[4 * lane];

    for (int tile = blockIdx.x * 8 + wid; tile < ntiles; tile += tstride) {
        const int row0 = tile * TILE;
        // lane r (r<16) holds indices for row r
        int mc0 = 0, mc1 = 0;
        if (lane < 16) {
            int ei = row0 + lane;
            int rr = ei < E ? ei : E - 1;
            mc0 = col0[rr]; mc1 = col1[rr];
        }

        // phase 1: T = tf32(relu(XW1h[c0]+XW1h[c1]+SW1[c0]+b1)), cooperative
        #pragma unroll 4
        for (int r = 0; r < 16; r++) {
            int c0r = __shfl_sync(FULLM, mc0, r);
            int c1r = __shfl_sync(FULLM, mc1, r);
            float4 a = *(const float4*)&g_XW1[(size_t)c0r * DD + 4 * lane];
            float4 b = *(const float4*)&g_XW1[(size_t)c1r * DD + 4 * lane];
            float4 s = *(const float4*)&g_SW1[(size_t)c0r * DD + 4 * lane];
            float4 t;
            t.x = tf32r(fmaxf(a.x + b.x + s.x + bb1.x, 0.f));
            t.y = tf32r(fmaxf(a.y + b.y + s.y + bb1.y, 0.f));
            t.z = tf32r(fmaxf(a.z + b.z + s.z + bb1.z, 0.f));
            t.w = tf32r(fmaxf(a.w + b.w + s.w + bb1.w, 0.f));
            *(float4*)&sA[SWA(r, lane, 0)] = t;
        }
        __syncwarp();

        float acc[16][4];
        ZERO_ACC16();
        WARP_GEMM_S(uW, uA);     // O2 = T @ W2
        __syncwarp();
        ACC_TO_SA(sA);           // raw O2 -> sA
        __syncwarp();

        // cooperative row epilogue: lgX = tf32(O2+b2); S1 += relu(O2+b2+x[c1])
        #pragma unroll 4
        for (int r = 0; r < 16; r++) {
            int gr = row0 + r;
            if (gr >= E) break;
            int c0r = __shfl_sync(FULLM, mc0, r);
            int c1r = __shfl_sync(FULLM, mc1, r);
            float4 ov = *(float4*)&sA[SWA(r, lane, 0)];
            ov.x += bb2.x; ov.y += bb2.y; ov.z += bb2.z; ov.w += bb2.w;
            float4 rr;
            rr.x = tf32r(ov.x); rr.y = tf32r(ov.y);
            rr.z = tf32r(ov.z); rr.w = tf32r(ov.w);
            *(float4*)&g_lgX[(size_t)gr * DD + 4 * lane] = rr;
            if (c0r != c1r) {
                float4 xs = *(const float4*)&x[(size_t)c1r * DD + 4 * lane];
                float4 v;
                v.x = fmaxf(ov.x + xs.x, 0.f);
                v.y = fmaxf(ov.y + xs.y, 0.f);
                v.z = fmaxf(ov.z + xs.z, 0.f);
                v.w = fmaxf(ov.w + xs.w, 0.f);
                red_add_v4(&Sout[(size_t)c1r * DD + 4 * lane], v);
            }
        }
        __syncwarp();
    }
}

// ---- k_mlp2: iteration 2, 2 GEMMs, cooperative gathers/scatters ------------
#define MLP2_SMEM ((2 * SW_WORDS + 8 * SA16_WORDS) * 4)   // 204800 B
__global__ void __launch_bounds__(256, 1)
k_mlp2(const int* __restrict__ col0, const int* __restrict__ col1,
       const float* __restrict__ b1, const float* __restrict__ b2,
       float* __restrict__ Sout,
       int E, int ntiles, int tstride)
{
    extern __shared__ float sm[];
    float* sW1 = sm;
    float* sW2 = sm + SW_WORDS;
    float* sAb = sm + 2 * SW_WORDS;

    const int tid  = threadIdx.x;
    const int wid  = tid >> 5, lane = tid & 31;
    const int ty   = lane >> 2, tx4 = lane & 3;

    float* sA = sAb + wid * SA16_WORDS;
    const uint32_t* uA  = (const uint32_t*)sA;
    const uint32_t* uW1 = (const uint32_t*)sW1;
    const uint32_t* uW2 = (const uint32_t*)sW2;
    const uint32_t sAu = smem_u32(sA);

    #pragma unroll
    for (int i = tid; i < 4096; i += 256) {
        int k = i >> 5, n4 = i & 31;
        *(float4*)&sW1[k * LDW + 4 * n4] = ((const float4*)g_Wr1)[i];
        *(float4*)&sW2[k * LDW + 4 * n4] = ((const float4*)g_Wr2)[i];
    }
    __syncthreads();

    const float4 bb1 = *(const float4*)&b1[4 * lane];
    const float4 bb2 = *(const float4*)&b2[4 * lane];

    int tile = blockIdx.x * 8 + wid;

    // prologue: stage first tile, row-contiguous cp.async
    if (tile < ntiles) {
        #pragma unroll
        for (int r = 0; r < 16; r++) {
            int gr = tile * TILE + r;
            if (gr >= E) gr = E - 1;
            cp_async16(sAu + 4 * SWA(r, lane, 0),
                       &g_lgX[(size_t)gr * DD + 4 * lane]);
        }
        CP_COMMIT();
    }

    for (; tile < ntiles; tile += tstride) {
        const int row0 = tile * TILE;
        int mc0 = 0, mc1 = 0;
        if (lane < 16) {
            int ei = row0 + lane;
            int rr = ei < E ? ei : E - 1;
            mc0 = col0[rr]; mc1 = col1[rr];
        }

        CP_WAIT0();
        __syncwarp();

        float acc[16][4];
        ZERO_ACC16();
        WARP_GEMM_S(uW1, uA);    // O1 = lgX @ W1
        __syncwarp();
        ACC_TO_SA(sA);           // raw O1 -> sA
        __syncwarp();

        // cooperative row phase: T = tf32(relu(O1 + SW1[c0] + b1)) in place
        #pragma unroll 4
        for (int r = 0; r < 16; r++) {
            int c0r = __shfl_sync(FULLM, mc0, r);
            float4 o1 = *(float4*)&sA[SWA(r, lane, 0)];
            float4 s  = *(const float4*)&g_SW1[(size_t)c0r * DD + 4 * lane];
            float4 t;
            t.x = tf32r(fmaxf(o1.x + s.x + bb1.x, 0.f));
            t.y = tf32r(fmaxf(o1.y + s.y + bb1.y, 0.f));
            t.z = tf32r(fmaxf(o1.z + s.z + bb1.z, 0.f));
            t.w = tf32r(fmaxf(o1.w + s.w + bb1.w, 0.f));
            *(float4*)&sA[SWA(r, lane, 0)] = t;
        }
        __syncwarp();

        ZERO_ACC16();
        WARP_GEMM_S(uW2, uA);    // O2 = T @ W2
        __syncwarp();
        ACC_TO_SA(sA);           // raw O2 -> sA
        __syncwarp();

        // cooperative final scatter: Sf[c1] += O2 + b2
        #pragma unroll 4
        for (int r = 0; r < 16; r++) {
            int gr = row0 + r;
            if (gr >= E) break;
            int c1r = __shfl_sync(FULLM, mc1, r);
            float4 ov = *(float4*)&sA[SWA(r, lane, 0)];
            ov.x += bb2.x; ov.y += bb2.y; ov.z += bb2.z; ov.w += bb2.w;
            red_add_v4(&Sout[(size_t)c1r * DD + 4 * lane], ov);
        }
        __syncwarp();

        // stage next tile
        {
            int nt = tile + tstride;
            if (nt < ntiles) {
                #pragma unroll
                for (int r = 0; r < 16; r++) {
                    int g2 = nt * TILE + r;
                    if (g2 >= E) g2 = E - 1;
                    cp_async16(sAu + 4 * SWA(r, lane, 0),
                               &g_lgX[(size_t)g2 * DD + 4 * lane]);
                }
                CP_COMMIT();
            }
        }
    }
}

// ----------------------- out = x + relu(Sf/cnt or 0) ------------------------
__global__ void k_fout(const float* __restrict__ x, float* __restrict__ out, int N)
{
    int idx = blockIdx.x * blockDim.x + threadIdx.x;
    int v = idx >> 5, q = idx & 31;
    if (v >= N) return;
    float c   = g_cnt[v];
    float inv = (c > 0.f) ? (1.f / c) : 0.f;
    float4 s  = ((const float4*)g_Sf)[(size_t)v * DV + q];
    float4 xv = ((const float4*)x)[(size_t)v * DV + q];
    float4 o;
    o.x = xv.x + fmaxf(s.x * inv, 0.f);
    o.y = xv.y + fmaxf(s.y * inv, 0.f);
    o.z = xv.z + fmaxf(s.z * inv, 0.f);
    o.w = xv.w + fmaxf(s.w * inv, 0.f);
    ((float4*)out)[(size_t)v * DV + q] = o;
}

// ---------------------------------------------------------------------------
extern "C" void kernel_launch(void* const* d_in, const int* in_sizes, int n_in,
                              void* d_out, int out_size)
{
    const float* x    = (const float*)d_in[0];
    const float* W1   = (const float*)d_in[1];
    const float* b1   = (const float*)d_in[2];
    const float* W2   = (const float*)d_in[3];
    const float* b2   = (const float*)d_in[4];
    const int*   col0 = (const int*)d_in[5];
    const int*   col1 = (const int*)d_in[6];
    // lg_src / lg_dst / edge_attr_idx are algebraically redundant.

    const int E = in_sizes[5];
    const int N = in_sizes[0] / DD;
    float* out = (float*)d_out;

    void *pS0, *pS1, *pSf, *pC, *pXW1, *pSW1;
    cudaGetSymbolAddress(&pS0,  g_S0);
    cudaGetSymbolAddress(&pS1,  g_S1);
    cudaGetSymbolAddress(&pSf,  g_Sf);
    cudaGetSymbolAddress(&pC,   g_cnt);
    cudaGetSymbolAddress(&pXW1, g_XW1);
    cudaGetSymbolAddress(&pSW1, g_SW1);

    cudaFuncSetAttribute((const void*)k_rw1,
                         cudaFuncAttributeMaxDynamicSharedMemorySize, RW1_SMEM);
    cudaFuncSetAttribute((const void*)k_mlp1,
                         cudaFuncAttributeMaxDynamicSharedMemorySize, MLP1_SMEM);
    cudaFuncSetAttribute((const void*)k_mlp2,
                         cudaFuncAttributeMaxDynamicSharedMemorySize, MLP2_SMEM);

    int smcount = 148;
    cudaDeviceGetAttribute(&smcount, cudaDevAttrMultiProcessorCount, 0);

    const int tpb = 256;
    const int nbE = (E * 32 + tpb - 1) / tpb;
    const int nbN = (N * 32 + tpb - 1) / tpb;
    const int ntiles  = (E + TILE - 1) / TILE;
    const int tstride = 8 * smcount;

    k_prep<<<(N * 32 + tpb - 1) / tpb, tpb>>>(W1, W2, (float4*)pS0, (float4*)pS1,
                                              (float4*)pSf, (float*)pC,
                                              N * 32, N);
    k_init<<<nbE, tpb>>>(x, col0, col1, E);

    // XW1h = (0.5 x) @ W1 ; SW1_0 = S0 @ W1 (one persistent launch)
    k_rw1<<<smcount, tpb, RW1_SMEM>>>(x, (float*)pXW1, N,
                                      (const float*)pS0, (float*)pSW1, N, 0.5f);
    // iteration 1 (slot 4 for ncu)
    k_mlp1<<<smcount, tpb, MLP1_SMEM>>>(col0, col1, x, b1, b2,
                                        (float*)pS1, E, ntiles, tstride);
    // SW1_1 = S1 @ W1
    k_rw1<<<smcount, tpb, RW1_SMEM>>>((const float*)pS1, (float*)pSW1, N,
                                      (const float*)pS1, (float*)pSW1, 0, 1.0f);
    // iteration 2 (final): Sf += lgX2
    k_mlp2<<<smcount, tpb, MLP2_SMEM>>>(col0, col1, b1, b2,
                                        (float*)pSf, E, ntiles, tstride);
    k_fout<<<nbN, tpb>>>(x, out, N);
}

// round 15
// speedup vs baseline: 1.4473x; 1.1023x over previous
#include <cuda_runtime.h>
#include <cstdint>

// ---------------------------------------------------------------------------
// LGNN GINE layer, algebraically collapsed, iteration-1 linearized through x:
//   S0[v]  = sum_{col1[i]==v, c0!=c1} relu(0.5(x[c0]+x[c1]) + x[v]) (k_init)
//   XW1h   = (0.5 x) @ W1 ; SW1_0 = S0 @ W1          (one persistent GEMM)
//   iter1: T = relu(XW1h[c0]+XW1h[c1]+SW1_0[c0]+b1); lgX1 = T@W2+b2
//          scatter S1 += relu(lgX1 + x[c1])           (k_mlp1: ONE gemm)
//   SW1_1  = S1 @ W1
//   iter2: lgX2 = relu(lgX1@W1 + SW1_1[c0] + b1)@W2 + b2 ; Sf += lgX2 (k_mlp2)
//   out    = x + relu(Sf / cnt)
// v3: warp-cooperative row gathers/scatters (R14 win) + higher warp counts:
// k_mlp1/k_rw1 at 12 warps, k_mlp2 at 10 warps (smem-budget limited).
// ---------------------------------------------------------------------------

#define DD   128
#define DV   32
#define MAXE 200000
#define MAXN 50000
#define TILE 16

__device__ float g_S0[(size_t)MAXN * DD];
__device__ float g_S1[(size_t)MAXN * DD];
__device__ float g_Sf[(size_t)MAXN * DD];
__device__ float g_SW1[(size_t)MAXN * DD];
__device__ float g_XW1[(size_t)MAXN * DD];
__device__ float g_lgX[(size_t)MAXE * DD];
__device__ float g_cnt[MAXN];
__device__ float g_Wr1[DD * DD];   // tf32-rounded W1, [k][n]
__device__ float g_Wr2[DD * DD];   // tf32-rounded W2, [k][n]

// ----------------------------- helpers --------------------------------------
__device__ __forceinline__ uint32_t smem_u32(const void* p) {
    uint32_t a;
    asm("{ .reg .u64 t; cvta.to.shared.u64 t, %1; cvt.u32.u64 %0, t; }"
        : "=r"(a) : "l"(p));
    return a;
}
__device__ __forceinline__ float tf32r(float f) {
    uint32_t u;
    asm("cvt.rna.tf32.f32 %0, %1;" : "=r"(u) : "f"(f));
    return __uint_as_float(u);
}
__device__ __forceinline__ void red_add_v4(float* p, float4 v) {
    asm volatile("red.global.add.v4.f32 [%0], {%1,%2,%3,%4};"
                 :: "l"(p), "f"(v.x), "f"(v.y), "f"(v.z), "f"(v.w) : "memory");
}
__device__ __forceinline__ void mma_tf32(float* d, uint32_t a0, uint32_t a1,
                                         uint32_t a2, uint32_t a3,
                                         uint32_t b0, uint32_t b1) {
    asm volatile(
        "mma.sync.aligned.m16n8k8.row.col.f32.tf32.tf32.f32 "
        "{%0,%1,%2,%3}, {%4,%5,%6,%7}, {%8,%9}, {%0,%1,%2,%3};"
        : "+f"(d[0]), "+f"(d[1]), "+f"(d[2]), "+f"(d[3])
        : "r"(a0), "r"(a1), "r"(a2), "r"(a3), "r"(b0), "r"(b1));
}
__device__ __forceinline__ void cp_async16(uint32_t dst, const void* src) {
    asm volatile("cp.async.cg.shared.global [%0], [%1], 16;"
                 :: "r"(dst), "l"(src) : "memory");
}
#define CP_COMMIT() asm volatile("cp.async.commit_group;" ::: "memory")
#define CP_WAIT0()  asm volatile("cp.async.wait_group 0;"  ::: "memory")
#define FULLM 0xffffffffu

#define LDW 136
// float4-granular XOR swizzle for A: row r, float4-col c4 (0..31), word ofs o
#define SWA(r, c4, o) (((r) << 7) + (((((c4) ^ ((r) & 7))) << 2) | (o)))

// warp GEMM: acc[16][4] += Aswz(16x128) @ Wsmem(128x128), frag coords ty/tx4
#define WARP_GEMM_S(UW, UA)                                                    \
    _Pragma("unroll 4")                                                        \
    for (int kk = 0; kk < 16; kk++) {                                          \
        uint32_t a0 = (UA)[SWA(ty,     kk * 2,     tx4)];                      \
        uint32_t a1 = (UA)[SWA(ty + 8, kk * 2,     tx4)];                      \
        uint32_t a2 = (UA)[SWA(ty,     kk * 2 + 1, tx4)];                      \
        uint32_t a3 = (UA)[SWA(ty + 8, kk * 2 + 1, tx4)];                      \
        _Pragma("unroll")                                                      \
        for (int n = 0; n < 16; n++) {                                         \
            uint32_t b0 = (UW)[(kk * 8 + tx4)     * LDW + 8 * n + ty];         \
            uint32_t b1r = (UW)[(kk * 8 + tx4 + 4) * LDW + 8 * n + ty];        \
            mma_tf32(acc[n], a0, a1, a2, a3, b0, b1r);                         \
        }                                                                      \
    }

#define ZERO_ACC16()                                                           \
    _Pragma("unroll")                                                          \
    for (int n = 0; n < 16; n++)                                               \
        _Pragma("unroll")                                                      \
        for (int j = 0; j < 4; j++) acc[n][j] = 0.f;

// fragment accumulators (raw, no bias) -> sA row-major
#define ACC_TO_SA(SA)                                                          \
    _Pragma("unroll")                                                          \
    for (int n = 0; n < 16; n++) {                                             \
        int c4 = 2 * n + (tx4 >> 1), o = (2 * tx4) & 3;                        \
        *(float2*)&(SA)[SWA(ty, c4, o)]     =                                  \
            make_float2(acc[n][0], acc[n][1]);                                 \
        *(float2*)&(SA)[SWA(ty + 8, c4, o)] =                                  \
            make_float2(acc[n][2], acc[n][3]);                                 \
    }

#define SW_WORDS   (128 * LDW)
#define SA16_WORDS (TILE * 128)

// ------------- prep: zero scratch/cnt + tf32-round weights ------------------
__global__ void k_prep(const float* __restrict__ W1, const float* __restrict__ W2,
                       float4* s0, float4* s1, float4* sf, float* cnt,
                       int n4, int n)
{
    int i = blockIdx.x * blockDim.x + threadIdx.x;
    float4 z = make_float4(0.f, 0.f, 0.f, 0.f);
    if (i < n4) { s0[i] = z; s1[i] = z; sf[i] = z; }
    if (i < n)  cnt[i] = 0.f;
    if (i < DD * DD) {
        g_Wr1[i] = tf32r(W1[i]);
        g_Wr2[i] = tf32r(W2[i]);
    }
}

// ---- init: scatter relu(0.5(x[c0]+x[c1]) + x[c1]) -> S0; cnt ---------------
__global__ void k_init(const float* __restrict__ x,
                       const int* __restrict__ col0,
                       const int* __restrict__ col1, int E)
{
    int idx = blockIdx.x * blockDim.x + threadIdx.x;
    int e = idx >> 5, q = idx & 31;
    if (e >= E) return;
    int c0 = col0[e], c1 = col1[e];
    if (q == 0) atomicAdd(&g_cnt[c1], 1.0f);
    if (c0 == c1) return;
    const float4* x4 = (const float4*)x;
    float4 a = x4[(size_t)c0 * DV + q];
    float4 b = x4[(size_t)c1 * DV + q];
    float4 v;
    v.x = fmaxf(0.5f * (a.x + b.x) + b.x, 0.f);
    v.y = fmaxf(0.5f * (a.y + b.y) + b.y, 0.f);
    v.z = fmaxf(0.5f * (a.z + b.z) + b.z, 0.f);
    v.w = fmaxf(0.5f * (a.w + b.w) + b.w, 0.f);
    red_add_v4(&g_S0[(size_t)c1 * DD + 4 * q], v);
}

// ---- k_rw1: persistent row-GEMM vs W1, 12 independent warps ----------------
#define RW1W 12
#define RW1_THR (RW1W * 32)
#define RW1_SMEM ((SW_WORDS + RW1W * SA16_WORDS) * 4)
__global__ void __launch_bounds__(RW1_THR, 1)
k_rw1(const float* __restrict__ A0, float* __restrict__ D0, int n0,
      const float* __restrict__ A1, float* __restrict__ D1, int n1,
      float c0f)
{
    extern __shared__ float sm[];
    float* sW  = sm;
    float* sAb = sm + SW_WORDS;

    const int tid  = threadIdx.x;
    const int wid  = tid >> 5, lane = tid & 31;
    const int ty   = lane >> 2, tx4 = lane & 3;

    float* sA = sAb + wid * SA16_WORDS;
    const uint32_t* uA = (const uint32_t*)sA;
    const uint32_t* uW = (const uint32_t*)sW;

    for (int i = tid; i < 4096; i += RW1_THR) {
        int k = i >> 5, n4 = i & 31;
        *(float4*)&sW[k * LDW + 4 * n4] = ((const float4*)g_Wr1)[i];
    }
    __syncthreads();

    const int ntot = n0 + n1;
    const int ntw  = (ntot + TILE - 1) / TILE;
    const int stride = RW1W * gridDim.x;

    for (int wt = blockIdx.x * RW1W + wid; wt < ntw; wt += stride) {
        const int row0 = wt * TILE;

        #pragma unroll 4
        for (int r = 0; r < 16; r++) {
            int R = row0 + r;
            if (R >= ntot) R = ntot - 1;
            const float* src;
            float cf;
            if (R < n0) { src = &A0[(size_t)R * DD]; cf = c0f; }
            else        { src = &A1[(size_t)(R - n0) * DD]; cf = 1.0f; }
            float4 s = *(const float4*)&src[4 * lane];
            float4 v;
            v.x = tf32r(cf * s.x); v.y = tf32r(cf * s.y);
            v.z = tf32r(cf * s.z); v.w = tf32r(cf * s.w);
            *(float4*)&sA[SWA(r, lane, 0)] = v;
        }
        __syncwarp();

        float acc[16][4];
        ZERO_ACC16();
        WARP_GEMM_S(uW, uA);
        __syncwarp();

        ACC_TO_SA(sA);
        __syncwarp();

        #pragma unroll 4
        for (int r = 0; r < 16; r++) {
            int gr = row0 + r;
            if (gr >= ntot) break;
            float* dst = (gr < n0) ? &D0[(size_t)gr * DD]
                                   : &D1[(size_t)(gr - n0) * DD];
            *(float4*)&dst[4 * lane] = *(float4*)&sA[SWA(r, lane, 0)];
        }
        __syncwarp();
    }
}

// ---- k_mlp1: iteration 1, GEMM1 replaced by cooperative row gathers --------
#define M1W 12
#define M1_THR (M1W * 32)
#define MLP1_SMEM ((SW_WORDS + M1W * SA16_WORDS) * 4)   // ~164 KB
__global__ void __launch_bounds__(M1_THR, 1)
k_mlp1(const int* __restrict__ col0, const int* __restrict__ col1,
       const float* __restrict__ x,
       const float* __restrict__ b1, const float* __restrict__ b2,
       float* __restrict__ Sout,
       int E, int ntiles, int tstride)
{
    extern __shared__ float sm[];
    float* sW2 = sm;
    float* sAb = sm + SW_WORDS;

    const int tid  = threadIdx.x;
    const int wid  = tid >> 5, lane = tid & 31;
    const int ty   = lane >> 2, tx4 = lane & 3;

    float* sA = sAb + wid * SA16_WORDS;
    const uint32_t* uA = (const uint32_t*)sA;
    const uint32_t* uW = (const uint32_t*)sW2;

    for (int i = tid; i < 4096; i += M1_THR) {
        int k = i >> 5, n4 = i & 31;
        *(float4*)&sW2[k * LDW + 4 * n4] = ((const float4*)g_Wr2)[i];
    }
    __syncthreads();

    const float4 bb1 = *(const float4*)&b1[4 * lane];
    const float4 bb2 = *(const float4*)&b2[4 * lane];

    for (int tile = blockIdx.x * M1W + wid; tile < ntiles; tile += tstride) {
        const int row0 = tile * TILE;
        int mc0 = 0, mc1 = 0;
        if (lane < 16) {
            int ei = row0 + lane;
            int rr = ei < E ? ei : E - 1;
            mc0 = col0[rr]; mc1 = col1[rr];
        }

        // phase 1: T = tf32(relu(XW1h[c0]+XW1h[c1]+SW1[c0]+b1)), cooperative
        #pragma unroll 4
        for (int r = 0; r < 16; r++) {
            int c0r = __shfl_sync(FULLM, mc0, r);
            int c1r = __shfl_sync(FULLM, mc1, r);
            float4 a = *(const float4*)&g_XW1[(size_t)c0r * DD + 4 * lane];
            float4 b = *(const float4*)&g_XW1[(size_t)c1r * DD + 4 * lane];
            float4 s = *(const float4*)&g_SW1[(size_t)c0r * DD + 4 * lane];
            float4 t;
            t.x = tf32r(fmaxf(a.x + b.x + s.x + bb1.x, 0.f));
            t.y = tf32r(fmaxf(a.y + b.y + s.y + bb1.y, 0.f));
            t.z = tf32r(fmaxf(a.z + b.z + s.z + bb1.z, 0.f));
            t.w = tf32r(fmaxf(a.w + b.w + s.w + bb1.w, 0.f));
            *(float4*)&sA[SWA(r, lane, 0)] = t;
        }
        __syncwarp();

        float acc[16][4];
        ZERO_ACC16();
        WARP_GEMM_S(uW, uA);     // O2 = T @ W2
        __syncwarp();
        ACC_TO_SA(sA);           // raw O2 -> sA
        __syncwarp();

        // cooperative row epilogue: lgX = tf32(O2+b2); S1 += relu(O2+b2+x[c1])
        #pragma unroll 4
        for (int r = 0; r < 16; r++) {
            int gr = row0 + r;
            if (gr >= E) break;
            int c0r = __shfl_sync(FULLM, mc0, r);
            int c1r = __shfl_sync(FULLM, mc1, r);
            float4 ov = *(float4*)&sA[SWA(r, lane, 0)];
            ov.x += bb2.x; ov.y += bb2.y; ov.z += bb2.z; ov.w += bb2.w;
            float4 rr;
            rr.x = tf32r(ov.x); rr.y = tf32r(ov.y);
            rr.z = tf32r(ov.z); rr.w = tf32r(ov.w);
            *(float4*)&g_lgX[(size_t)gr * DD + 4 * lane] = rr;
            if (c0r != c1r) {
                float4 xs = *(const float4*)&x[(size_t)c1r * DD + 4 * lane];
                float4 v;
                v.x = fmaxf(ov.x + xs.x, 0.f);
                v.y = fmaxf(ov.y + xs.y, 0.f);
                v.z = fmaxf(ov.z + xs.z, 0.f);
                v.w = fmaxf(ov.w + xs.w, 0.f);
                red_add_v4(&Sout[(size_t)c1r * DD + 4 * lane], v);
            }
        }
        __syncwarp();
    }
}

// ---- k_mlp2: iteration 2, 2 GEMMs, cooperative gathers/scatters, 10 warps --
#define M2W 10
#define M2_THR (M2W * 32)
#define MLP2_SMEM ((2 * SW_WORDS + M2W * SA16_WORDS) * 4)   // ~216 KB
__global__ void __launch_bounds__(M2_THR, 1)
k_mlp2(const int* __restrict__ col0, const int* __restrict__ col1,
       const float* __restrict__ b1, const float* __restrict__ b2,
       float* __restrict__ Sout,
       int E, int ntiles, int tstride)
{
    extern __shared__ float sm[];
    float* sW1 = sm;
    float* sW2 = sm + SW_WORDS;
    float* sAb = sm + 2 * SW_WORDS;

    const int tid  = threadIdx.x;
    const int wid  = tid >> 5, lane = tid & 31;
    const int ty   = lane >> 2, tx4 = lane & 3;

    float* sA = sAb + wid * SA16_WORDS;
    const uint32_t* uA  = (const uint32_t*)sA;
    const uint32_t* uW1 = (const uint32_t*)sW1;
    const uint32_t* uW2 = (const uint32_t*)sW2;
    const uint32_t sAu = smem_u32(sA);

    for (int i = tid; i < 4096; i += M2_THR) {
        int k = i >> 5, n4 = i & 31;
        *(float4*)&sW1[k * LDW + 4 * n4] = ((const float4*)g_Wr1)[i];
        *(float4*)&sW2[k * LDW + 4 * n4] = ((const float4*)g_Wr2)[i];
    }
    __syncthreads();

    const float4 bb1 = *(const float4*)&b1[4 * lane];
    const float4 bb2 = *(const float4*)&b2[4 * lane];

    int tile = blockIdx.x * M2W + wid;

    if (tile < ntiles) {
        #pragma unroll
        for (int r = 0; r < 16; r++) {
            int gr = tile * TILE + r;
            if (gr >= E) gr = E - 1;
            cp_async16(sAu + 4 * SWA(r, lane, 0),
                       &g_lgX[(size_t)gr * DD + 4 * lane]);
        }
        CP_COMMIT();
    }

    for (; tile < ntiles; tile += tstride) {
        const int row0 = tile * TILE;
        int mc0 = 0, mc1 = 0;
        if (lane < 16) {
            int ei = row0 + lane;
            int rr = ei < E ? ei : E - 1;
            mc0 = col0[rr]; mc1 = col1[rr];
        }

        CP_WAIT0();
        __syncwarp();

        float acc[16][4];
        ZERO_ACC16();
        WARP_GEMM_S(uW1, uA);    // O1 = lgX @ W1
        __syncwarp();
        ACC_TO_SA(sA);           // raw O1 -> sA
        __syncwarp();

        // cooperative row phase: T = tf32(relu(O1 + SW1[c0] + b1)) in place
        #pragma unroll 4
        for (int r = 0; r < 16; r++) {
            int c0r = __shfl_sync(FULLM, mc0, r);
            float4 o1 = *(float4*)&sA[SWA(r, lane, 0)];
            float4 s  = *(const float4*)&g_SW1[(size_t)c0r * DD + 4 * lane];
            float4 t;
            t.x = tf32r(fmaxf(o1.x + s.x + bb1.x, 0.f));
            t.y = tf32r(fmaxf(o1.y + s.y + bb1.y, 0.f));
            t.z = tf32r(fmaxf(o1.z + s.z + bb1.z, 0.f));
            t.w = tf32r(fmaxf(o1.w + s.w + bb1.w, 0.f));
            *(float4*)&sA[SWA(r, lane, 0)] = t;
        }
        __syncwarp();

        ZERO_ACC16();
        WARP_GEMM_S(uW2, uA);    // O2 = T @ W2
        __syncwarp();
        ACC_TO_SA(sA);           // raw O2 -> sA
        __syncwarp();

        // cooperative final scatter: Sf[c1] += O2 + b2
        #pragma unroll 4
        for (int r = 0; r < 16; r++) {
            int gr = row0 + r;
            if (gr >= E) break;
            int c1r = __shfl_sync(FULLM, mc1, r);
            float4 ov = *(float4*)&sA[SWA(r, lane, 0)];
            ov.x += bb2.x; ov.y += bb2.y; ov.z += bb2.z; ov.w += bb2.w;
            red_add_v4(&Sout[(size_t)c1r * DD + 4 * lane], ov);
        }
        __syncwarp();

        {
            int nt = tile + tstride;
            if (nt < ntiles) {
                #pragma unroll
                for (int r = 0; r < 16; r++) {
                    int g2 = nt * TILE + r;
                    if (g2 >= E) g2 = E - 1;
                    cp_async16(sAu + 4 * SWA(r, lane, 0),
                               &g_lgX[(size_t)g2 * DD + 4 * lane]);
                }
                CP_COMMIT();
            }
        }
    }
}

// ----------------------- out = x + relu(Sf/cnt or 0) ------------------------
__global__ void k_fout(const float* __restrict__ x, float* __restrict__ out, int N)
{
    int idx = blockIdx.x * blockDim.x + threadIdx.x;
    int v = idx >> 5, q = idx & 31;
    if (v >= N) return;
    float c   = g_cnt[v];
    float inv = (c > 0.f) ? (1.f / c) : 0.f;
    float4 s  = ((const float4*)g_Sf)[(size_t)v * DV + q];
    float4 xv = ((const float4*)x)[(size_t)v * DV + q];
    float4 o;
    o.x = xv.x + fmaxf(s.x * inv, 0.f);
    o.y = xv.y + fmaxf(s.y * inv, 0.f);
    o.z = xv.z + fmaxf(s.z * inv, 0.f);
    o.w = xv.w + fmaxf(s.w * inv, 0.f);
    ((float4*)out)[(size_t)v * DV + q] = o;
}

// ---------------------------------------------------------------------------
extern "C" void kernel_launch(void* const* d_in, const int* in_sizes, int n_in,
                              void* d_out, int out_size)
{
    const float* x    = (const float*)d_in[0];
    const float* W1   = (const float*)d_in[1];
    const float* b1   = (const float*)d_in[2];
    const float* W2   = (const float*)d_in[3];
    const float* b2   = (const float*)d_in[4];
    const int*   col0 = (const int*)d_in[5];
    const int*   col1 = (const int*)d_in[6];
    // lg_src / lg_dst / edge_attr_idx are algebraically redundant.

    const int E = in_sizes[5];
    const int N = in_sizes[0] / DD;
    float* out = (float*)d_out;

    void *pS0, *pS1, *pSf, *pC, *pXW1, *pSW1;
    cudaGetSymbolAddress(&pS0,  g_S0);
    cudaGetSymbolAddress(&pS1,  g_S1);
    cudaGetSymbolAddress(&pSf,  g_Sf);
    cudaGetSymbolAddress(&pC,   g_cnt);
    cudaGetSymbolAddress(&pXW1, g_XW1);
    cudaGetSymbolAddress(&pSW1, g_SW1);

    cudaFuncSetAttribute((const void*)k_rw1,
                         cudaFuncAttributeMaxDynamicSharedMemorySize, RW1_SMEM);
    cudaFuncSetAttribute((const void*)k_mlp1,
                         cudaFuncAttributeMaxDynamicSharedMemorySize, MLP1_SMEM);
    cudaFuncSetAttribute((const void*)k_mlp2,
                         cudaFuncAttributeMaxDynamicSharedMemorySize, MLP2_SMEM);

    int smcount = 148;
    cudaDeviceGetAttribute(&smcount, cudaDevAttrMultiProcessorCount, 0);

    const int tpb = 256;
    const int nbE = (E * 32 + tpb - 1) / tpb;
    const int nbN = (N * 32 + tpb - 1) / tpb;
    const int ntiles   = (E + TILE - 1) / TILE;
    const int tstride1 = M1W * smcount;
    const int tstride2 = M2W * smcount;

    k_prep<<<(N * 32 + tpb - 1) / tpb, tpb>>>(W1, W2, (float4*)pS0, (float4*)pS1,
                                              (float4*)pSf, (float*)pC,
                                              N * 32, N);
    k_init<<<nbE, tpb>>>(x, col0, col1, E);

    // XW1h = (0.5 x) @ W1 ; SW1_0 = S0 @ W1 (one persistent launch)
    k_rw1<<<smcount, RW1_THR, RW1_SMEM>>>(x, (float*)pXW1, N,
                                          (const float*)pS0, (float*)pSW1, N, 0.5f);
    // iteration 1 (slot 4 for ncu)
    k_mlp1<<<smcount, M1_THR, MLP1_SMEM>>>(col0, col1, x, b1, b2,
                                           (float*)pS1, E, ntiles, tstride1);
    // SW1_1 = S1 @ W1
    k_rw1<<<smcount, RW1_THR, RW1_SMEM>>>((const float*)pS1, (float*)pSW1, N,
                                          (const float*)pS1, (float*)pSW1, 0, 1.0f);
    // iteration 2 (final): Sf += lgX2
    k_mlp2<<<smcount, M2_THR, MLP2_SMEM>>>(col0, col1, b1, b2,
                                           (float*)pSf, E, ntiles, tstride2);
    k_fout<<<nbN, tpb>>>(x, out, N);
}

// round 16
// speedup vs baseline: 1.5382x; 1.0628x over previous
#include <cuda_runtime.h>
#include <cstdint>

// ---------------------------------------------------------------------------
// LGNN GINE layer, algebraically collapsed, iteration-1 linearized through x:
//   S0[v]  = sum_{col1[i]==v, c0!=c1} relu(0.5(x[c0]+x[c1]) + x[v]) (k_init)
//   XW1h   = (0.5 x) @ W1 ; SW1_0 = S0 @ W1          (one persistent GEMM)
//   iter1: T = relu(XW1h[c0]+XW1h[c1]+SW1_0[c0]+b1); lgX1 = T@W2+b2
//          scatter S1 += relu(lgX1 + x[c1])           (k_mlp1: ONE gemm)
//   SW1_1  = S1 @ W1
//   iter2: lgX2 = relu(lgX1@W1 + SW1_1[c0] + b1)@W2 + b2 ; Sf += lgX2 (k_mlp2)
//   out    = x + relu(Sf / cnt)
// v4: warp-cooperative row gathers/scatters + max warp counts:
// k_mlp1/k_rw1 at 14 warps, k_mlp2 at 11 warps (smem caps).
// ---------------------------------------------------------------------------

#define DD   128
#define DV   32
#define MAXE 200000
#define MAXN 50000
#define TILE 16

__device__ float g_S0[(size_t)MAXN * DD];
__device__ float g_S1[(size_t)MAXN * DD];
__device__ float g_Sf[(size_t)MAXN * DD];
__device__ float g_SW1[(size_t)MAXN * DD];
__device__ float g_XW1[(size_t)MAXN * DD];
__device__ float g_lgX[(size_t)MAXE * DD];
__device__ float g_cnt[MAXN];
__device__ float g_Wr1[DD * DD];   // tf32-rounded W1, [k][n]
__device__ float g_Wr2[DD * DD];   // tf32-rounded W2, [k][n]

// ----------------------------- helpers --------------------------------------
__device__ __forceinline__ uint32_t smem_u32(const void* p) {
    uint32_t a;
    asm("{ .reg .u64 t; cvta.to.shared.u64 t, %1; cvt.u32.u64 %0, t; }"
        : "=r"(a) : "l"(p));
    return a;
}
__device__ __forceinline__ float tf32r(float f) {
    uint32_t u;
    asm("cvt.rna.tf32.f32 %0, %1;" : "=r"(u) : "f"(f));
    return __uint_as_float(u);
}
__device__ __forceinline__ void red_add_v4(float* p, float4 v) {
    asm volatile("red.global.add.v4.f32 [%0], {%1,%2,%3,%4};"
                 :: "l"(p), "f"(v.x), "f"(v.y), "f"(v.z), "f"(v.w) : "memory");
}
__device__ __forceinline__ void mma_tf32(float* d, uint32_t a0, uint32_t a1,
                                         uint32_t a2, uint32_t a3,
                                         uint32_t b0, uint32_t b1) {
    asm volatile(
        "mma.sync.aligned.m16n8k8.row.col.f32.tf32.tf32.f32 "
        "{%0,%1,%2,%3}, {%4,%5,%6,%7}, {%8,%9}, {%0,%1,%2,%3};"
        : "+f"(d[0]), "+f"(d[1]), "+f"(d[2]), "+f"(d[3])
        : "r"(a0), "r"(a1), "r"(a2), "r"(a3), "r"(b0), "r"(b1));
}
__device__ __forceinline__ void cp_async16(uint32_t dst, const void* src) {
    asm volatile("cp.async.cg.shared.global [%0], [%1], 16;"
                 :: "r"(dst), "l"(src) : "memory");
}
#define CP_COMMIT() asm volatile("cp.async.commit_group;" ::: "memory")
#define CP_WAIT0()  asm volatile("cp.async.wait_group 0;"  ::: "memory")
#define FULLM 0xffffffffu

#define LDW 136
// float4-granular XOR swizzle for A: row r, float4-col c4 (0..31), word ofs o
#define SWA(r, c4, o) (((r) << 7) + (((((c4) ^ ((r) & 7))) << 2) | (o)))

// warp GEMM: acc[16][4] += Aswz(16x128) @ Wsmem(128x128), frag coords ty/tx4
#define WARP_GEMM_S(UW, UA)                                                    \
    _Pragma("unroll 4")                                                        \
    for (int kk = 0; kk < 16; kk++) {                                          \
        uint32_t a0 = (UA)[SWA(ty,     kk * 2,     tx4)];                      \
        uint32_t a1 = (UA)[SWA(ty + 8, kk * 2,     tx4)];                      \
        uint32_t a2 = (UA)[SWA(ty,     kk * 2 + 1, tx4)];                      \
        uint32_t a3 = (UA)[SWA(ty + 8, kk * 2 + 1, tx4)];                      \
        _Pragma("unroll")                                                      \
        for (int n = 0; n < 16; n++) {                                         \
            uint32_t b0 = (UW)[(kk * 8 + tx4)     * LDW + 8 * n + ty];         \
            uint32_t b1r = (UW)[(kk * 8 + tx4 + 4) * LDW + 8 * n + ty];        \
            mma_tf32(acc[n], a0, a1, a2, a3, b0, b1r);                         \
        }                                                                      \
    }

#define ZERO_ACC16()                                                           \
    _Pragma("unroll")                                                          \
    for (int n = 0; n < 16; n++)                                               \
        _Pragma("unroll")                                                      \
        for (int j = 0; j < 4; j++) acc[n][j] = 0.f;

// fragment accumulators (raw, no bias) -> sA row-major
#define ACC_TO_SA(SA)                                                          \
    _Pragma("unroll")                                                          \
    for (int n = 0; n < 16; n++) {                                             \
        int c4 = 2 * n + (tx4 >> 1), o = (2 * tx4) & 3;                        \
        *(float2*)&(SA)[SWA(ty, c4, o)]     =                                  \
            make_float2(acc[n][0], acc[n][1]);                                 \
        *(float2*)&(SA)[SWA(ty + 8, c4, o)] =                                  \
            make_float2(acc[n][2], acc[n][3]);                                 \
    }

#define SW_WORDS   (128 * LDW)
#define SA16_WORDS (TILE * 128)

// ------------- prep: zero scratch/cnt + tf32-round weights ------------------
__global__ void k_prep(const float* __restrict__ W1, const float* __restrict__ W2,
                       float4* s0, float4* s1, float4* sf, float* cnt,
                       int n4, int n)
{
    int i = blockIdx.x * blockDim.x + threadIdx.x;
    float4 z = make_float4(0.f, 0.f, 0.f, 0.f);
    if (i < n4) { s0[i] = z; s1[i] = z; sf[i] = z; }
    if (i < n)  cnt[i] = 0.f;
    if (i < DD * DD) {
        g_Wr1[i] = tf32r(W1[i]);
        g_Wr2[i] = tf32r(W2[i]);
    }
}

// ---- init: scatter relu(0.5(x[c0]+x[c1]) + x[c1]) -> S0; cnt ---------------
__global__ void k_init(const float* __restrict__ x,
                       const int* __restrict__ col0,
                       const int* __restrict__ col1, int E)
{
    int idx = blockIdx.x * blockDim.x + threadIdx.x;
    int e = idx >> 5, q = idx & 31;
    if (e >= E) return;
    int c0 = col0[e], c1 = col1[e];
    if (q == 0) atomicAdd(&g_cnt[c1], 1.0f);
    if (c0 == c1) return;
    const float4* x4 = (const float4*)x;
    float4 a = x4[(size_t)c0 * DV + q];
    float4 b = x4[(size_t)c1 * DV + q];
    float4 v;
    v.x = fmaxf(0.5f * (a.x + b.x) + b.x, 0.f);
    v.y = fmaxf(0.5f * (a.y + b.y) + b.y, 0.f);
    v.z = fmaxf(0.5f * (a.z + b.z) + b.z, 0.f);
    v.w = fmaxf(0.5f * (a.w + b.w) + b.w, 0.f);
    red_add_v4(&g_S0[(size_t)c1 * DD + 4 * q], v);
}

// ---- k_rw1: persistent row-GEMM vs W1, 14 independent warps ----------------
#define RW1W 14
#define RW1_THR (RW1W * 32)
#define RW1_SMEM ((SW_WORDS + RW1W * SA16_WORDS) * 4)
__global__ void __launch_bounds__(RW1_THR, 1)
k_rw1(const float* __restrict__ A0, float* __restrict__ D0, int n0,
      const float* __restrict__ A1, float* __restrict__ D1, int n1,
      float c0f)
{
    extern __shared__ float sm[];
    float* sW  = sm;
    float* sAb = sm + SW_WORDS;

    const int tid  = threadIdx.x;
    const int wid  = tid >> 5, lane = tid & 31;
    const int ty   = lane >> 2, tx4 = lane & 3;

    float* sA = sAb + wid * SA16_WORDS;
    const uint32_t* uA = (const uint32_t*)sA;
    const uint32_t* uW = (const uint32_t*)sW;

    for (int i = tid; i < 4096; i += RW1_THR) {
        int k = i >> 5, n4 = i & 31;
        *(float4*)&sW[k * LDW + 4 * n4] = ((const float4*)g_Wr1)[i];
    }
    __syncthreads();

    const int ntot = n0 + n1;
    const int ntw  = (ntot + TILE - 1) / TILE;
    const int stride = RW1W * gridDim.x;

    for (int wt = blockIdx.x * RW1W + wid; wt < ntw; wt += stride) {
        const int row0 = wt * TILE;

        #pragma unroll 4
        for (int r = 0; r < 16; r++) {
            int R = row0 + r;
            if (R >= ntot) R = ntot - 1;
            const float* src;
            float cf;
            if (R < n0) { src = &A0[(size_t)R * DD]; cf = c0f; }
            else        { src = &A1[(size_t)(R - n0) * DD]; cf = 1.0f; }
            float4 s = *(const float4*)&src[4 * lane];
            float4 v;
            v.x = tf32r(cf * s.x); v.y = tf32r(cf * s.y);
            v.z = tf32r(cf * s.z); v.w = tf32r(cf * s.w);
            *(float4*)&sA[SWA(r, lane, 0)] = v;
        }
        __syncwarp();

        float acc[16][4];
        ZERO_ACC16();
        WARP_GEMM_S(uW, uA);
        __syncwarp();

        ACC_TO_SA(sA);
        __syncwarp();

        #pragma unroll 4
        for (int r = 0; r < 16; r++) {
            int gr = row0 + r;
            if (gr >= ntot) break;
            float* dst = (gr < n0) ? &D0[(size_t)gr * DD]
                                   : &D1[(size_t)(gr - n0) * DD];
            *(float4*)&dst[4 * lane] = *(float4*)&sA[SWA(r, lane, 0)];
        }
        __syncwarp();
    }
}

// ---- k_mlp1: iteration 1, GEMM1 replaced by cooperative row gathers --------
#define M1W 14
#define M1_THR (M1W * 32)
#define MLP1_SMEM ((SW_WORDS + M1W * SA16_WORDS) * 4)   // ~180 KB
__global__ void __launch_bounds__(M1_THR, 1)
k_mlp1(const int* __restrict__ col0, const int* __restrict__ col1,
       const float* __restrict__ x,
       const float* __restrict__ b1, const float* __restrict__ b2,
       float* __restrict__ Sout,
       int E, int ntiles, int tstride)
{
    extern __shared__ float sm[];
    float* sW2 = sm;
    float* sAb = sm + SW_WORDS;

    const int tid  = threadIdx.x;
    const int wid  = tid >> 5, lane = tid & 31;
    const int ty   = lane >> 2, tx4 = lane & 3;

    float* sA = sAb + wid * SA16_WORDS;
    const uint32_t* uA = (const uint32_t*)sA;
    const uint32_t* uW = (const uint32_t*)sW2;

    for (int i = tid; i < 4096; i += M1_THR) {
        int k = i >> 5, n4 = i & 31;
        *(float4*)&sW2[k * LDW + 4 * n4] = ((const float4*)g_Wr2)[i];
    }
    __syncthreads();

    const float4 bb1 = *(const float4*)&b1[4 * lane];
    const float4 bb2 = *(const float4*)&b2[4 * lane];

    for (int tile = blockIdx.x * M1W + wid; tile < ntiles; tile += tstride) {
        const int row0 = tile * TILE;
        int mc0 = 0, mc1 = 0;
        if (lane < 16) {
            int ei = row0 + lane;
            int rr = ei < E ? ei : E - 1;
            mc0 = col0[rr]; mc1 = col1[rr];
        }

        // phase 1: T = tf32(relu(XW1h[c0]+XW1h[c1]+SW1[c0]+b1)), cooperative
        #pragma unroll 4
        for (int r = 0; r < 16; r++) {
            int c0r = __shfl_sync(FULLM, mc0, r);
            int c1r = __shfl_sync(FULLM, mc1, r);
            float4 a = *(const float4*)&g_XW1[(size_t)c0r * DD + 4 * lane];
            float4 b = *(const float4*)&g_XW1[(size_t)c1r * DD + 4 * lane];
            float4 s = *(const float4*)&g_SW1[(size_t)c0r * DD + 4 * lane];
            float4 t;
            t.x = tf32r(fmaxf(a.x + b.x + s.x + bb1.x, 0.f));
            t.y = tf32r(fmaxf(a.y + b.y + s.y + bb1.y, 0.f));
            t.z = tf32r(fmaxf(a.z + b.z + s.z + bb1.z, 0.f));
            t.w = tf32r(fmaxf(a.w + b.w + s.w + bb1.w, 0.f));
            *(float4*)&sA[SWA(r, lane, 0)] = t;
        }
        __syncwarp();

        float acc[16][4];
        ZERO_ACC16();
        WARP_GEMM_S(uW, uA);     // O2 = T @ W2
        __syncwarp();
        ACC_TO_SA(sA);           // raw O2 -> sA
        __syncwarp();

        // cooperative row epilogue: lgX = tf32(O2+b2); S1 += relu(O2+b2+x[c1])
        #pragma unroll 4
        for (int r = 0; r < 16; r++) {
            int gr = row0 + r;
            if (gr >= E) break;
            int c0r = __shfl_sync(FULLM, mc0, r);
            int c1r = __shfl_sync(FULLM, mc1, r);
            float4 ov = *(float4*)&sA[SWA(r, lane, 0)];
            ov.x += bb2.x; ov.y += bb2.y; ov.z += bb2.z; ov.w += bb2.w;
            float4 rr;
            rr.x = tf32r(ov.x); rr.y = tf32r(ov.y);
            rr.z = tf32r(ov.z); rr.w = tf32r(ov.w);
            *(float4*)&g_lgX[(size_t)gr * DD + 4 * lane] = rr;
            if (c0r != c1r) {
                float4 xs = *(const float4*)&x[(size_t)c1r * DD + 4 * lane];
                float4 v;
                v.x = fmaxf(ov.x + xs.x, 0.f);
                v.y = fmaxf(ov.y + xs.y, 0.f);
                v.z = fmaxf(ov.z + xs.z, 0.f);
                v.w = fmaxf(ov.w + xs.w, 0.f);
                red_add_v4(&Sout[(size_t)c1r * DD + 4 * lane], v);
            }
        }
        __syncwarp();
    }
}

// ---- k_mlp2: iteration 2, 2 GEMMs, cooperative gathers/scatters, 11 warps --
#define M2W 11
#define M2_THR (M2W * 32)
#define MLP2_SMEM ((2 * SW_WORDS + M2W * SA16_WORDS) * 4)   // 229376 B
__global__ void __launch_bounds__(M2_THR, 1)
k_mlp2(const int* __restrict__ col0, const int* __restrict__ col1,
       const float* __restrict__ b1, const float* __restrict__ b2,
       float* __restrict__ Sout,
       int E, int ntiles, int tstride)
{
    extern __shared__ float sm[];
    float* sW1 = sm;
    float* sW2 = sm + SW_WORDS;
    float* sAb = sm + 2 * SW_WORDS;

    const int tid  = threadIdx.x;
    const int wid  = tid >> 5, lane = tid & 31;
    const int ty   = lane >> 2, tx4 = lane & 3;

    float* sA = sAb + wid * SA16_WORDS;
    const uint32_t* uA  = (const uint32_t*)sA;
    const uint32_t* uW1 = (const uint32_t*)sW1;
    const uint32_t* uW2 = (const uint32_t*)sW2;
    const uint32_t sAu = smem_u32(sA);

    for (int i = tid; i < 4096; i += M2_THR) {
        int k = i >> 5, n4 = i & 31;
        *(float4*)&sW1[k * LDW + 4 * n4] = ((const float4*)g_Wr1)[i];
        *(float4*)&sW2[k * LDW + 4 * n4] = ((const float4*)g_Wr2)[i];
    }
    __syncthreads();

    const float4 bb1 = *(const float4*)&b1[4 * lane];
    const float4 bb2 = *(const float4*)&b2[4 * lane];

    int tile = blockIdx.x * M2W + wid;

    if (tile < ntiles) {
        #pragma unroll
        for (int r = 0; r < 16; r++) {
            int gr = tile * TILE + r;
            if (gr >= E) gr = E - 1;
            cp_async16(sAu + 4 * SWA(r, lane, 0),
                       &g_lgX[(size_t)gr * DD + 4 * lane]);
        }
        CP_COMMIT();
    }

    for (; tile < ntiles; tile += tstride) {
        const int row0 = tile * TILE;
        int mc0 = 0, mc1 = 0;
        if (lane < 16) {
            int ei = row0 + lane;
            int rr = ei < E ? ei : E - 1;
            mc0 = col0[rr]; mc1 = col1[rr];
        }

        CP_WAIT0();
        __syncwarp();

        float acc[16][4];
        ZERO_ACC16();
        WARP_GEMM_S(uW1, uA);    // O1 = lgX @ W1
        __syncwarp();
        ACC_TO_SA(sA);           // raw O1 -> sA
        __syncwarp();

        // cooperative row phase: T = tf32(relu(O1 + SW1[c0] + b1)) in place
        #pragma unroll 4
        for (int r = 0; r < 16; r++) {
            int c0r = __shfl_sync(FULLM, mc0, r);
            float4 o1 = *(float4*)&sA[SWA(r, lane, 0)];
            float4 s  = *(const float4*)&g_SW1[(size_t)c0r * DD + 4 * lane];
            float4 t;
            t.x = tf32r(fmaxf(o1.x + s.x + bb1.x, 0.f));
            t.y = tf32r(fmaxf(o1.y + s.y + bb1.y, 0.f));
            t.z = tf32r(fmaxf(o1.z + s.z + bb1.z, 0.f));
            t.w = tf32r(fmaxf(o1.w + s.w + bb1.w, 0.f));
            *(float4*)&sA[SWA(r, lane, 0)] = t;
        }
        __syncwarp();

        ZERO_ACC16();
        WARP_GEMM_S(uW2, uA);    // O2 = T @ W2
        __syncwarp();
        ACC_TO_SA(sA);           // raw O2 -> sA
        __syncwarp();

        // cooperative final scatter: Sf[c1] += O2 + b2
        #pragma unroll 4
        for (int r = 0; r < 16; r++) {
            int gr = row0 + r;
            if (gr >= E) break;
            int c1r = __shfl_sync(FULLM, mc1, r);
            float4 ov = *(float4*)&sA[SWA(r, lane, 0)];
            ov.x += bb2.x; ov.y += bb2.y; ov.z += bb2.z; ov.w += bb2.w;
            red_add_v4(&Sout[(size_t)c1r * DD + 4 * lane], ov);
        }
        __syncwarp();

        {
            int nt = tile + tstride;
            if (nt < ntiles) {
                #pragma unroll
                for (int r = 0; r < 16; r++) {
                    int g2 = nt * TILE + r;
                    if (g2 >= E) g2 = E - 1;
                    cp_async16(sAu + 4 * SWA(r, lane, 0),
                               &g_lgX[(size_t)g2 * DD + 4 * lane]);
                }
                CP_COMMIT();
            }
        }
    }
}

// ----------------------- out = x + relu(Sf/cnt or 0) ------------------------
__global__ void k_fout(const float* __restrict__ x, float* __restrict__ out, int N)
{
    int idx = blockIdx.x * blockDim.x + threadIdx.x;
    int v = idx >> 5, q = idx & 31;
    if (v >= N) return;
    float c   = g_cnt[v];
    float inv = (c > 0.f) ? (1.f / c) : 0.f;
    float4 s  = ((const float4*)g_Sf)[(size_t)v * DV + q];
    float4 xv = ((const float4*)x)[(size_t)v * DV + q];
    float4 o;
    o.x = xv.x + fmaxf(s.x * inv, 0.f);
    o.y = xv.y + fmaxf(s.y * inv, 0.f);
    o.z = xv.z + fmaxf(s.z * inv, 0.f);
    o.w = xv.w + fmaxf(s.w * inv, 0.f);
    ((float4*)out)[(size_t)v * DV + q] = o;
}

// ---------------------------------------------------------------------------
extern "C" void kernel_launch(void* const* d_in, const int* in_sizes, int n_in,
                              void* d_out, int out_size)
{
    const float* x    = (const float*)d_in[0];
    const float* W1   = (const float*)d_in[1];
    const float* b1   = (const float*)d_in[2];
    const float* W2   = (const float*)d_in[3];
    const float* b2   = (const float*)d_in[4];
    const int*   col0 = (const int*)d_in[5];
    const int*   col1 = (const int*)d_in[6];
    // lg_src / lg_dst / edge_attr_idx are algebraically redundant.

    const int E = in_sizes[5];
    const int N = in_sizes[0] / DD;
    float* out = (float*)d_out;

    void *pS0, *pS1, *pSf, *pC, *pXW1, *pSW1;
    cudaGetSymbolAddress(&pS0,  g_S0);
    cudaGetSymbolAddress(&pS1,  g_S1);
    cudaGetSymbolAddress(&pSf,  g_Sf);
    cudaGetSymbolAddress(&pC,   g_cnt);
    cudaGetSymbolAddress(&pXW1, g_XW1);
    cudaGetSymbolAddress(&pSW1, g_SW1);

    cudaFuncSetAttribute((const void*)k_rw1,
                         cudaFuncAttributeMaxDynamicSharedMemorySize, RW1_SMEM);
    cudaFuncSetAttribute((const void*)k_mlp1,
                         cudaFuncAttributeMaxDynamicSharedMemorySize, MLP1_SMEM);
    cudaFuncSetAttribute((const void*)k_mlp2,
                         cudaFuncAttributeMaxDynamicSharedMemorySize, MLP2_SMEM);

    int smcount = 148;
    cudaDeviceGetAttribute(&smcount, cudaDevAttrMultiProcessorCount, 0);

    const int tpb = 256;
    const int nbE = (E * 32 + tpb - 1) / tpb;
    const int nbN = (N * 32 + tpb - 1) / tpb;
    const int ntiles   = (E + TILE - 1) / TILE;
    const int tstride1 = M1W * smcount;
    const int tstride2 = M2W * smcount;

    k_prep<<<(N * 32 + tpb - 1) / tpb, tpb>>>(W1, W2, (float4*)pS0, (float4*)pS1,
                                              (float4*)pSf, (float*)pC,
                                              N * 32, N);
    k_init<<<nbE, tpb>>>(x, col0, col1, E);

    // XW1h = (0.5 x) @ W1 ; SW1_0 = S0 @ W1 (one persistent launch)
    k_rw1<<<smcount, RW1_THR, RW1_SMEM>>>(x, (float*)pXW1, N,
                                          (const float*)pS0, (float*)pSW1, N, 0.5f);
    // iteration 1 (slot 4 for ncu)
    k_mlp1<<<smcount, M1_THR, MLP1_SMEM>>>(col0, col1, x, b1, b2,
                                           (float*)pS1, E, ntiles, tstride1);
    // SW1_1 = S1 @ W1
    k_rw1<<<smcount, RW1_THR, RW1_SMEM>>>((const float*)pS1, (float*)pSW1, N,
                                          (const float*)pS1, (float*)pSW1, 0, 1.0f);
    // iteration 2 (final): Sf += lgX2
    k_mlp2<<<smcount, M2_THR, MLP2_SMEM>>>(col0, col1, b1, b2,
                                           (float*)pSf, E, ntiles, tstride2);
    k_fout<<<nbN, tpb>>>(x, out, N);
}